// round 13
// baseline (speedup 1.0000x reference)
#include <cuda_runtime.h>
#include <cuda_bf16.h>
#include <cstdint>

#define D_MODEL 2048
#define SEQ     2048
#define BATCH   2
#define NHEADS  16
#define HDIM    128
#define M_TOK   (BATCH*SEQ)   // 4096

#if defined(__CUDA_ARCH_FEAT_SM103_ALL) || defined(__CUDA_ARCH_FEAT_SM100_ALL) || \
    (defined(__CUDA_ARCH_SPECIFIC__) && (__CUDA_ARCH_SPECIFIC__ >= 1000))
#define HAS_TCGEN05 1
#else
#define HAS_TCGEN05 0
#endif

// ---- persistent scratch ----
__device__ float g_v[M_TOK * D_MODEL];     // fp32 V (packed to V^T by pack_v)

__device__ __nv_bfloat16 g_xh[M_TOK * D_MODEL];
__device__ __nv_bfloat16 g_xl[M_TOK * D_MODEL];
__device__ __nv_bfloat16 g_chh[M_TOK * D_MODEL];   // packed ctx (written by attn)
__device__ __nv_bfloat16 g_cll[M_TOK * D_MODEL];
__device__ __nv_bfloat16 g_wh[4][D_MODEL * D_MODEL];
__device__ __nv_bfloat16 g_wl[4][D_MODEL * D_MODEL];

__device__ __nv_bfloat16 g_aqh[M_TOK * D_MODEL];   // Q tiles: [bh][rt16][2ch x 16KB]
__device__ __nv_bfloat16 g_aql[M_TOK * D_MODEL];
__device__ __nv_bfloat16 g_akh[M_TOK * D_MODEL];   // K tiles: [bh][kt32][2ch x 8KB]
__device__ __nv_bfloat16 g_akl[M_TOK * D_MODEL];
__device__ __nv_bfloat16 g_avh[M_TOK * D_MODEL];   // V^T tiles: [bh][kt32][16KB]
__device__ __nv_bfloat16 g_avl[M_TOK * D_MODEL];

// ============================================================
// PTX helpers
// ============================================================
__device__ __forceinline__ uint32_t smem_u32(const void* p) {
    uint32_t a;
    asm("{ .reg .u64 t; cvta.to.shared.u64 t, %1; cvt.u32.u64 %0, t; }" : "=r"(a) : "l"(p));
    return a;
}
__device__ __forceinline__ uint32_t elect_one_pred() {
    uint32_t p;
    asm volatile("{ .reg .pred p; elect.sync _|p, 0xFFFFFFFF; selp.b32 %0, 1, 0, p; }" : "=r"(p));
    return p;
}
__device__ __forceinline__ uint32_t cluster_rank() {
    uint32_t r;
    asm("mov.u32 %0, %%cluster_ctarank;" : "=r"(r));
    return r;
}
static constexpr uint64_t SMEM_DESC_BASE_SW128 =
    (uint64_t(2) << 61) | (uint64_t(1) << 46) | (uint64_t(64) << 32) | (uint64_t(1) << 16);
#define MAKE_SMEM_DESC(base_addr) \
    (SMEM_DESC_BASE_SW128 | ((uint64_t)((base_addr) >> 4) & 0x3FFF))
#define SMEM_SWIZZLE_128B(off) ((off) ^ (((off) >> 3) & 0x70))

#define MBARRIER_INIT(mbar, count) \
    asm volatile("mbarrier.init.shared.b64 [%0], %1;" \
                 :: "r"((uint32_t)(mbar)), "r"((uint32_t)(count)) : "memory")
#define MBARRIER_INVAL(mbar) \
    asm volatile("mbarrier.inval.shared.b64 [%0];" :: "r"((uint32_t)(mbar)) : "memory")
#define MBARRIER_EXPECT_TX(mbar, bytes) \
    asm volatile("mbarrier.arrive.expect_tx.shared.b64 _, [%0], %1;" \
                 :: "r"((uint32_t)(mbar)), "r"((uint32_t)(bytes)) : "memory")
#define MBARRIER_ARRIVE(mbar) \
    asm volatile("mbarrier.arrive.shared.b64 _, [%0];" :: "r"((uint32_t)(mbar)) : "memory")
#define MBARRIER_ARRIVE_CLUSTER(mbar, rank) \
    asm volatile("{ .reg .b32 ra; mapa.shared::cluster.u32 ra, %0, %1; " \
                 "mbarrier.arrive.shared::cluster.b64 _, [ra]; }" \
                 :: "r"((uint32_t)(mbar)), "r"((uint32_t)(rank)) : "memory")
#define MBARRIER_WAIT_PARITY(mbar, parity) do {                                          \
    uint32_t _m = (uint32_t)(mbar);                                                      \
    uint32_t _p = (uint32_t)(parity);                                                    \
    uint32_t _done;                                                                      \
    asm volatile("{ .reg .pred p; mbarrier.try_wait.parity.acquire.cta.shared::cta.b64 " \
                 "p, [%1], %2; selp.b32 %0, 1, 0, p; }"                                  \
                 : "=r"(_done) : "r"(_m), "r"(_p) : "memory");                           \
    if (!_done) {                                                                        \
        asm volatile("{ .reg .pred P1; WL_%=: "                                          \
                     "mbarrier.try_wait.parity.acquire.cta.shared::cta.b64 P1, [%0], %1, 0x989680; " \
                     "@P1 bra.uni WD_%=; bra.uni WL_%=; WD_%=: }"                        \
                     :: "r"(_m), "r"(_p) : "memory");                                    \
    }                                                                                    \
} while (0)

#define CLUSTER_SYNC() do { \
    asm volatile("barrier.cluster.arrive.aligned;" ::: "memory"); \
    asm volatile("barrier.cluster.wait.aligned;" ::: "memory"); \
} while (0)

#define BULK_CP(dst_smem, src_gmem, bytes, mbar) \
    asm volatile("cp.async.bulk.shared::cluster.global.mbarrier::complete_tx::bytes " \
                 "[%0], [%1], %2, [%3];" \
                 :: "r"((uint32_t)(dst_smem)), "l"(src_gmem), "r"((uint32_t)(bytes)), \
                    "r"((uint32_t)(mbar)) : "memory")

#if HAS_TCGEN05
#define TCGEN05_ALLOC(smem_addr, nCols) \
    asm volatile("tcgen05.alloc.cta_group::1.sync.aligned.shared::cta.b32 [%0], %1;" \
                 :: "r"((uint32_t)(smem_addr)), "r"((uint32_t)(nCols)) : "memory")
#define TCGEN05_DEALLOC(tmem_addr, nCols) \
    asm volatile("tcgen05.dealloc.cta_group::1.sync.aligned.b32 %0, %1;" \
                 :: "r"(tmem_addr), "r"((uint32_t)(nCols)))
#define TCGEN05_RELINQUISH() \
    asm volatile("tcgen05.relinquish_alloc_permit.cta_group::1.sync.aligned;")
#define TCGEN05_ALLOC_CG2(smem_addr, nCols) \
    asm volatile("tcgen05.alloc.cta_group::2.sync.aligned.shared::cta.b32 [%0], %1;" \
                 :: "r"((uint32_t)(smem_addr)), "r"((uint32_t)(nCols)) : "memory")
#define TCGEN05_DEALLOC_CG2(tmem_addr, nCols) \
    asm volatile("tcgen05.dealloc.cta_group::2.sync.aligned.b32 %0, %1;" \
                 :: "r"(tmem_addr), "r"((uint32_t)(nCols)))
#define TCGEN05_RELINQUISH_CG2() \
    asm volatile("tcgen05.relinquish_alloc_permit.cta_group::2.sync.aligned;")
#define TCGEN05_COMMIT(mbar) \
    asm volatile("tcgen05.commit.cta_group::1.mbarrier::arrive::one.shared::cluster.b64 [%0];" \
                 :: "r"((uint32_t)(mbar)) : "memory")
#define TCGEN05_COMMIT_MC_CG2(mbar, mask) \
    asm volatile("tcgen05.commit.cta_group::2.mbarrier::arrive::one.shared::cluster" \
                 ".multicast::cluster.b64 [%0], %1;" \
                 :: "r"((uint32_t)(mbar)), "h"((uint16_t)(mask)) : "memory")
#define TCGEN05_FENCE_AFTER() \
    asm volatile("tcgen05.fence::after_thread_sync;" ::: "memory")
#define TCGEN05_FENCE_BEFORE() \
    asm volatile("tcgen05.fence::before_thread_sync;" ::: "memory")
#define TCGEN05_WAIT_LD() \
    asm volatile("tcgen05.wait::ld.sync.aligned;" ::: "memory")
#define TCGEN05_WAIT_ST() \
    asm volatile("tcgen05.wait::st.sync.aligned;" ::: "memory")

#define TCGEN05_LD_32X32B_X32(r, tmem_addr) \
    asm volatile( \
        "tcgen05.ld.sync.aligned.32x32b.x32.b32 " \
        "{%0, %1, %2, %3, %4, %5, %6, %7, " \
        " %8, %9, %10, %11, %12, %13, %14, %15, " \
        " %16, %17, %18, %19, %20, %21, %22, %23, " \
        " %24, %25, %26, %27, %28, %29, %30, %31}, [%32];" \
        : "=r"((r)[0]),  "=r"((r)[1]),  "=r"((r)[2]),  "=r"((r)[3]), \
          "=r"((r)[4]),  "=r"((r)[5]),  "=r"((r)[6]),  "=r"((r)[7]), \
          "=r"((r)[8]),  "=r"((r)[9]),  "=r"((r)[10]), "=r"((r)[11]), \
          "=r"((r)[12]), "=r"((r)[13]), "=r"((r)[14]), "=r"((r)[15]), \
          "=r"((r)[16]), "=r"((r)[17]), "=r"((r)[18]), "=r"((r)[19]), \
          "=r"((r)[20]), "=r"((r)[21]), "=r"((r)[22]), "=r"((r)[23]), \
          "=r"((r)[24]), "=r"((r)[25]), "=r"((r)[26]), "=r"((r)[27]), \
          "=r"((r)[28]), "=r"((r)[29]), "=r"((r)[30]), "=r"((r)[31]) \
        : "r"(tmem_addr))

#define TCGEN05_ST_32X32B_X32(tmem_addr, r) \
    asm volatile( \
        "tcgen05.st.sync.aligned.32x32b.x32.b32 [%0], " \
        "{%1, %2, %3, %4, %5, %6, %7, %8, " \
        " %9, %10, %11, %12, %13, %14, %15, %16, " \
        " %17, %18, %19, %20, %21, %22, %23, %24, " \
        " %25, %26, %27, %28, %29, %30, %31, %32};" \
        :: "r"(tmem_addr), \
           "r"((r)[0]),  "r"((r)[1]),  "r"((r)[2]),  "r"((r)[3]), \
           "r"((r)[4]),  "r"((r)[5]),  "r"((r)[6]),  "r"((r)[7]), \
           "r"((r)[8]),  "r"((r)[9]),  "r"((r)[10]), "r"((r)[11]), \
           "r"((r)[12]), "r"((r)[13]), "r"((r)[14]), "r"((r)[15]), \
           "r"((r)[16]), "r"((r)[17]), "r"((r)[18]), "r"((r)[19]), \
           "r"((r)[20]), "r"((r)[21]), "r"((r)[22]), "r"((r)[23]), \
           "r"((r)[24]), "r"((r)[25]), "r"((r)[26]), "r"((r)[27]), \
           "r"((r)[28]), "r"((r)[29]), "r"((r)[30]), "r"((r)[31]) \
        : "memory")

#define TCGEN05_ST_32X32B_X16(tmem_addr, r) \
    asm volatile( \
        "tcgen05.st.sync.aligned.32x32b.x16.b32 [%0], " \
        "{%1, %2, %3, %4, %5, %6, %7, %8, " \
        " %9, %10, %11, %12, %13, %14, %15, %16};" \
        :: "r"(tmem_addr), \
           "r"((r)[0]),  "r"((r)[1]),  "r"((r)[2]),  "r"((r)[3]), \
           "r"((r)[4]),  "r"((r)[5]),  "r"((r)[6]),  "r"((r)[7]), \
           "r"((r)[8]),  "r"((r)[9]),  "r"((r)[10]), "r"((r)[11]), \
           "r"((r)[12]), "r"((r)[13]), "r"((r)[14]), "r"((r)[15]) \
        : "memory")

__device__ __forceinline__ void mma_f16_ts(uint32_t d_tmem, uint32_t a_tmem, uint64_t b_desc,
                                           uint32_t idesc, uint32_t enable) {
    asm volatile(
        "{\n\t"
        ".reg .pred p;\n\t"
        "setp.ne.u32 p, %4, 0;\n\t"
        "tcgen05.mma.cta_group::1.kind::f16 [%0], [%1], %2, %3, {%5, %5, %5, %5}, p;\n\t"
        "}"
        :: "r"(d_tmem), "r"(a_tmem), "l"(b_desc), "r"(idesc), "r"(enable), "r"(0u)
        : "memory");
}
// cg2 SS bf16 MMA (M=256 across the pair; 8-word disable mask)
__device__ __forceinline__ void mma_f16_ss_cg2(uint32_t d_tmem, uint64_t a_desc, uint64_t b_desc,
                                               uint32_t idesc, uint32_t enable) {
    asm volatile(
        "{\n\t"
        ".reg .pred p;\n\t"
        "setp.ne.u32 p, %4, 0;\n\t"
        "tcgen05.mma.cta_group::2.kind::f16 [%0], %1, %2, %3, "
        "{%5, %5, %5, %5, %5, %5, %5, %5}, p;\n\t"
        "}"
        :: "r"(d_tmem), "l"(a_desc), "l"(b_desc), "r"(idesc), "r"(enable), "r"(0u)
        : "memory");
}
#endif  // HAS_TCGEN05

__device__ __forceinline__ void split_bf16(float f, __nv_bfloat16& h, __nv_bfloat16& l) {
    h = __float2bfloat16(f);
    l = __float2bfloat16(f - __bfloat162float(h));
}

// ============================================================
// Merged split+pack (unchanged)
// ============================================================
#define XN8 (M_TOK * D_MODEL / 8)
#define WN8 (D_MODEL * D_MODEL / 8)

__global__ __launch_bounds__(256) void split_all(
    const float* __restrict__ x, const float* __restrict__ W0,
    const float* __restrict__ W1, const float* __restrict__ W2,
    const float* __restrict__ W3)
{
    int i = blockIdx.x * blockDim.x + threadIdx.x;
    const float* src;
    __nv_bfloat16 *hi, *lo;
    int nrt, li;
    if (i < XN8) {
        src = x; hi = g_xh; lo = g_xl; nrt = 32; li = i;
    } else {
        int w = (i - XN8) >> 19;
        li = (i - XN8) & (WN8 - 1);
        src = (w == 0) ? W0 : (w == 1) ? W1 : (w == 2) ? W2 : W3;
        hi = g_wh[w]; lo = g_wl[w]; nrt = 16;
    }
    int elem = li * 8;
    int row = elem >> 11;
    int col = elem & 2047;
    int rt = row >> 7, r = row & 127;
    int c  = col >> 6, kc = col & 63;
    size_t tb = ((size_t)(c * nrt + rt)) << 14;
    uint32_t so = SMEM_SWIZZLE_128B((uint32_t)(r * 128 + kc * 2));

    float4 v0 = ((const float4*)src)[(size_t)li * 2];
    float4 v1 = ((const float4*)src)[(size_t)li * 2 + 1];
    float f[8] = {v0.x, v0.y, v0.z, v0.w, v1.x, v1.y, v1.z, v1.w};
    __align__(16) __nv_bfloat16 h[8], l[8];
#pragma unroll
    for (int j = 0; j < 8; j++) split_bf16(f[j], h[j], l[j]);
    *(uint4*)((char*)hi + tb + so) = *(uint4*)h;
    *(uint4*)((char*)lo + tb + so) = *(uint4*)l;
}

// ============================================================
// V^T packer (unchanged)
// ============================================================
__global__ __launch_bounds__(256) void pack_v()
{
    int i = blockIdx.x * blockDim.x + threadIdx.x;
    int elem = i * 8;
    int tok = elem >> 11, col = elem & 2047;
    int b = tok >> 11, s = tok & 2047;
    int h = col >> 7, d = col & 127;
    int bh = b * 16 + h;
    int kt = s >> 6, sc = s & 63;
    size_t tb = ((size_t)(bh * 32 + kt)) << 14;
    const float* src = g_v + (size_t)tok * 2048 + col;
    float4 v0 = *(const float4*)src, v1 = *(const float4*)(src + 4);
    float f[8] = {v0.x, v0.y, v0.z, v0.w, v1.x, v1.y, v1.z, v1.w};
#pragma unroll
    for (int j = 0; j < 8; j++) {
        __nv_bfloat16 hh, ll;
        split_bf16(f[j], hh, ll);
        uint32_t off = SMEM_SWIZZLE_128B((uint32_t)((d + j) * 128 + sc * 2));
        *(__nv_bfloat16*)((char*)g_avh + tb + off) = hh;
        *(__nv_bfloat16*)((char*)g_avl + tb + off) = ll;
    }
}

// ============================================================
// tcgen05 GEMM, cta_group::2, cluster (2,1,1) [pair along x].
// bx = blockIdx.x>>1 (256-col block, shared by pair);
// rank = ctarank (blockIdx.x&1); rm = blockIdx.y*2 + rank (own A rows).
// Each CTA: 128 A-rows + half of B (tile 2bx+rank). 3 stages x 64KB.
// barriers: full[3]@64+16s(tx), peer_full[3]@112+16s, cdone[3]@160+16s
// ============================================================
#define NCH  32
#define NRT_A 32
#define NRT_W 16
#define TIL  16384
#define STG  (4 * TIL)
#define SMB0 1024
#define GEMM_SMEM (SMB0 + 3 * STG)     // 197632
#define GEMM_IDESC_CG2 0x10400490u     // F32, BF16xBF16, M=256, N=256

__global__ __launch_bounds__(256) __cluster_dims__(2, 1, 1) void gemm_tc(
    int mode_base, const float* __restrict__ b0, const float* __restrict__ b1,
    const float* __restrict__ b2, const float* __restrict__ b3,
    float* __restrict__ out)
{
#if HAS_TCGEN05
    extern __shared__ char sm[];
    const uint32_t smb = smem_u32(sm);
    const int tid = threadIdx.x;
    const int wid = tid >> 5;
    const int lid = tid & 31;
    const uint32_t rank = cluster_rank();
    const int bx = blockIdx.x >> 1;            // 256-col block (shared by pair)
    const int rm = blockIdx.y * 2 + (int)rank; // own A row tile
    const int mode = mode_base + blockIdx.z;

    const __nv_bfloat16* Ah = (mode < 3) ? g_xh : g_chh;
    const __nv_bfloat16* Al = (mode < 3) ? g_xl : g_cll;
    const __nv_bfloat16* Bh = g_wh[mode];
    const __nv_bfloat16* Bl = g_wl[mode];
    const float* bias = (mode == 0) ? b0 : (mode == 1) ? b1 : (mode == 2) ? b2 : b3;
    const float alpha = (mode == 0) ? 0.08838834764831845f : 1.0f;

    if (wid == 0) TCGEN05_ALLOC_CG2(smb + 0, 256);
    if (tid == 0) {
#pragma unroll
        for (int s = 0; s < 3; ++s) {
            MBARRIER_INIT(smb + 64 + 16 * s, 1);     // full (tx, own loads)
            MBARRIER_INIT(smb + 112 + 16 * s, 1);    // peer_full (rank1 -> leader)
            MBARRIER_INIT(smb + 160 + 16 * s, 1);    // cdone (cg2 commit mc)
        }
    }
    __syncthreads();
    CLUSTER_SYNC();   // barriers + smem visible before peer ops

    uint32_t tmem;
    asm volatile("ld.shared.b32 %0, [%1];" : "=r"(tmem) : "r"(smb + 0));

    if (wid == 0 && elect_one_pred()) {
#define LOAD_CHUNK(c, s)                                                        \
        do {                                                                    \
            uint32_t st = smb + SMB0 + (s) * STG;                               \
            uint32_t fb = smb + 64 + 16 * (s);                                  \
            size_t ao = ((size_t)((c) * NRT_A + rm)) << 14;                     \
            size_t bo = ((size_t)((c) * NRT_W + 2 * bx + (int)rank)) << 14;     \
            MBARRIER_EXPECT_TX(fb, 4 * TIL);                                    \
            BULK_CP(st,           (const char*)Ah + ao, TIL, fb);               \
            BULK_CP(st + TIL,     (const char*)Al + ao, TIL, fb);               \
            BULK_CP(st + 2 * TIL, (const char*)Bh + bo, TIL, fb);               \
            BULK_CP(st + 3 * TIL, (const char*)Bl + bo, TIL, fb);               \
        } while (0)

        LOAD_CHUNK(0, 0);
        LOAD_CHUNK(1, 1);
        LOAD_CHUNK(2, 2);

        for (int c = 0; c < NCH; ++c) {
            int s = c % 3, ph = (c / 3) & 1;
            MBARRIER_WAIT_PARITY(smb + 64 + 16 * s, ph);       // own data ready
            if (rank == 0) {
                MBARRIER_WAIT_PARITY(smb + 112 + 16 * s, ph);  // peer half ready
                uint32_t st = smb + SMB0 + s * STG;
                uint64_t dAh = MAKE_SMEM_DESC(st);
                uint64_t dAl = MAKE_SMEM_DESC(st + TIL);
                uint64_t dBh = MAKE_SMEM_DESC(st + 2 * TIL);
                uint64_t dBl = MAKE_SMEM_DESC(st + 3 * TIL);
#pragma unroll
                for (int ks = 0; ks < 4; ++ks) {
                    mma_f16_ss_cg2(tmem, dAh + ks * 2, dBh + ks * 2, GEMM_IDESC_CG2, (c | ks) != 0);
                    mma_f16_ss_cg2(tmem, dAl + ks * 2, dBh + ks * 2, GEMM_IDESC_CG2, 1);
                    mma_f16_ss_cg2(tmem, dAh + ks * 2, dBl + ks * 2, GEMM_IDESC_CG2, 1);
                }
                TCGEN05_COMMIT_MC_CG2(smb + 160 + 16 * s, 3);
            } else {
                MBARRIER_ARRIVE_CLUSTER(smb + 112 + 16 * s, 0);  // tell leader
            }
            if (c + 3 < NCH) {
                MBARRIER_WAIT_PARITY(smb + 160 + 16 * s, ph);   // MMA(c) done -> stage free
                LOAD_CHUNK(c + 3, s);
            }
        }
        MBARRIER_WAIT_PARITY(smb + 160 + 16 * ((NCH - 1) % 3), ((NCH - 1) / 3) & 1);
#undef LOAD_CHUNK
    }
    __syncthreads();
    TCGEN05_FENCE_AFTER();

    // epilogue: this CTA's TMEM = its own 128 rows x all 256 cols
    const int wg = wid >> 2;
    const int sub = wid & 3;
    const int m = rm * 128 + sub * 32 + lid;
    const int hd = bx * 2 + wg;
    const int b_ = m >> 11, s_ = m & 2047;
    const int bh2 = b_ * 16 + hd;
    __align__(16) __nv_bfloat16 hv[8], lv[8];

#pragma unroll
    for (int cb = 0; cb < 4; ++cb) {
        uint32_t r[32];
        TCGEN05_LD_32X32B_X32(r, tmem + wg * 128 + cb * 32);
        TCGEN05_WAIT_LD();
        int n0 = bx * 256 + wg * 128 + cb * 32;

        if (mode == 3) {
            float* crow = out + (size_t)m * D_MODEL;
#pragma unroll
            for (int j = 0; j < 32; j += 4) {
                float4 o;
                o.x = __uint_as_float(r[j + 0]) + bias[n0 + j + 0];
                o.y = __uint_as_float(r[j + 1]) + bias[n0 + j + 1];
                o.z = __uint_as_float(r[j + 2]) + bias[n0 + j + 2];
                o.w = __uint_as_float(r[j + 3]) + bias[n0 + j + 3];
                *(float4*)(crow + n0 + j) = o;
            }
        } else if (mode == 2) {
            float* crow = g_v + (size_t)m * D_MODEL;
#pragma unroll
            for (int j = 0; j < 32; j += 4) {
                float4 o;
                o.x = __uint_as_float(r[j + 0]) + bias[n0 + j + 0];
                o.y = __uint_as_float(r[j + 1]) + bias[n0 + j + 1];
                o.z = __uint_as_float(r[j + 2]) + bias[n0 + j + 2];
                o.w = __uint_as_float(r[j + 3]) + bias[n0 + j + 3];
                *(float4*)(crow + n0 + j) = o;
            }
        } else {
            size_t tb;
            uint32_t rr;
            char *dh, *dl;
            if (mode == 0) {
                int rt2 = s_ >> 7; rr = s_ & 127;
                tb = ((size_t)((bh2 * 16 + rt2) * 2 + (cb >> 1))) << 14;
                dh = (char*)g_aqh + tb; dl = (char*)g_aql + tb;
            } else {
                int kt = s_ >> 6; rr = s_ & 63;
                tb = ((size_t)((bh2 * 32 + kt) * 2 + (cb >> 1))) << 13;
                dh = (char*)g_akh + tb; dl = (char*)g_akl + tb;
            }
            int kcb = (cb & 1) * 32;
#pragma unroll
            for (int j0 = 0; j0 < 32; j0 += 8) {
#pragma unroll
                for (int j = 0; j < 8; ++j) {
                    float f = (__uint_as_float(r[j0 + j]) + bias[n0 + j0 + j]) * alpha;
                    split_bf16(f, hv[j], lv[j]);
                }
                uint32_t so = SMEM_SWIZZLE_128B((uint32_t)(rr * 128 + (kcb + j0) * 2));
                *(uint4*)(dh + so) = *(uint4*)hv;
                *(uint4*)(dl + so) = *(uint4*)lv;
            }
        }
    }
    TCGEN05_FENCE_BEFORE();

    __syncthreads();
    CLUSTER_SYNC();   // no CTA exits while peer MMA/smem-read may be in flight
    if (tid == 0) {
#pragma unroll
        for (int s = 0; s < 3; ++s) {
            MBARRIER_INVAL(smb + 64 + 16 * s);
            MBARRIER_INVAL(smb + 112 + 16 * s);
            MBARRIER_INVAL(smb + 160 + 16 * s);
        }
    }
    __syncthreads();
    if (wid == 0) {
        TCGEN05_RELINQUISH_CG2();
        TCGEN05_DEALLOC_CG2(tmem, 256);
    }
    CLUSTER_SYNC();
#endif
}

// ============================================================
// tcgen05 flash attention (R11 8-warp softmax version, no clusters)
// ============================================================
#define AOFF_LBUF 1024
#define AOFF_MASK 2048
#define AOFF_K    10240
#define AOFF_V    75776
#define AOFF_QS   (AOFF_V + 65536)
#define ATTN_SMEM 206848
#define IDESC_S   0x8100490u
#define IDESC_PV  0x8200490u

__global__ __launch_bounds__(288) void attn_tc(const float* __restrict__ mask)
{
#if HAS_TCGEN05
    extern __shared__ char sm[];
    const uint32_t smb = smem_u32(sm);
    const int tid = threadIdx.x;
    const int wid = tid >> 5;
    const int lid = tid & 31;
    const int rt = blockIdx.x;
    const int bh = blockIdx.y;
    const int b = bh >> 4;

    if (wid == 0) TCGEN05_ALLOC(smb + 0, 512);
    if (tid == 0) {
        MBARRIER_INIT(smb + 64, 1);    // qbar (tx)
        MBARRIER_INIT(smb + 80, 4);    // qdone
#pragma unroll
        for (int s = 0; s < 2; ++s) {
            MBARRIER_INIT(smb + 96 + 16 * s, 1);    // full (tx)
            MBARRIER_INIT(smb + 128 + 16 * s, 1);   // s_full (commit)
            MBARRIER_INIT(smb + 160 + 16 * s, 8);   // smax_free
            MBARRIER_INIT(smb + 192 + 16 * s, 8);   // p_ready
            MBARRIER_INIT(smb + 224 + 16 * s, 1);   // pv_done (commit)
        }
    }
    for (int j = tid; j < SEQ; j += 288) {
        float mv = mask[b * SEQ + j];
        ((float*)(sm + AOFF_MASK))[j] = (1.0f - mv) * -1e30f;
    }
    __syncthreads();

    uint32_t tmem;
    asm volatile("ld.shared.b32 %0, [%1];" : "=r"(tmem) : "r"(smb + 0));

    // ---------------- control warp ----------------
    if (wid == 8) {
        if (elect_one_pred()) {
#define LOADKV(c)                                                          \
            do {                                                           \
                size_t kb = ((size_t)(bh * 32 + (c))) << 14;               \
                uint32_t kst = smb + AOFF_K + ((c) & 1) * 32768;           \
                uint32_t vst = smb + AOFF_V + ((c) & 3) * 32768;           \
                uint32_t fb = smb + 96 + 16 * ((c) & 1);                   \
                MBARRIER_EXPECT_TX(fb, 65536);                             \
                BULK_CP(kst,         (const char*)g_akh + kb, 16384, fb);  \
                BULK_CP(kst + 16384, (const char*)g_akl + kb, 16384, fb);  \
                BULK_CP(vst,         (const char*)g_avh + kb, 16384, fb);  \
                BULK_CP(vst + 16384, (const char*)g_avl + kb, 16384, fb);  \
            } while (0)

            {
                size_t qb = ((size_t)(bh * 16 + rt)) << 15;
                MBARRIER_EXPECT_TX(smb + 64, 65536);
                BULK_CP(smb + AOFF_QS,         (const char*)g_aqh + qb, 32768, smb + 64);
                BULK_CP(smb + AOFF_QS + 32768, (const char*)g_aql + qb, 32768, smb + 64);
                LOADKV(0);
                LOADKV(1);
            }
            MBARRIER_WAIT_PARITY(smb + 80, 0);
            TCGEN05_FENCE_AFTER();

            const uint32_t qh = tmem + 384, ql = tmem + 448;

            for (int i = 0; i < 32; ++i) {
                const int sb = i & 1;
                MBARRIER_WAIT_PARITY(smb + 96 + 16 * sb, (i >> 1) & 1);
                if (i >= 2) MBARRIER_WAIT_PARITY(smb + 160 + 16 * sb, ((i - 2) >> 1) & 1);
                {
                    uint32_t kst = smb + AOFF_K + sb * 32768;
                    uint32_t sreg = tmem + sb * 64;
#pragma unroll
                    for (int st = 0; st < 8; ++st) {
                        uint64_t bh_ = MAKE_SMEM_DESC(kst + (st >> 2) * 8192) + (st & 3) * 2;
                        uint64_t bl_ = MAKE_SMEM_DESC(kst + 16384 + (st >> 2) * 8192) + (st & 3) * 2;
                        mma_f16_ts(sreg, qh + st * 8, bh_, IDESC_S, st != 0);
                        mma_f16_ts(sreg, ql + st * 8, bh_, IDESC_S, 1);
                        mma_f16_ts(sreg, qh + st * 8, bl_, IDESC_S, 1);
                    }
                    TCGEN05_COMMIT(smb + 128 + 16 * sb);
                }
                if (i >= 1) {
                    const int j = i - 1, pb = j & 1, pj = (j >> 1) & 1;
                    MBARRIER_WAIT_PARITY(smb + 192 + 16 * pb, pj);
                    TCGEN05_FENCE_AFTER();
                    uint32_t vst = smb + AOFF_V + (j & 3) * 32768;
                    uint64_t dVh = MAKE_SMEM_DESC(vst);
                    uint64_t dVl = MAKE_SMEM_DESC(vst + 16384);
#pragma unroll
                    for (int ks = 0; ks < 4; ++ks) {
                        uint32_t ah = tmem + 256 + pb * 64 + ks * 8;
                        uint32_t al = tmem + 288 + pb * 64 + ks * 8;
                        mma_f16_ts(tmem + 128, ah, dVh + ks * 2, IDESC_PV, (j | ks) != 0);
                        mma_f16_ts(tmem + 128, al, dVh + ks * 2, IDESC_PV, 1);
                        mma_f16_ts(tmem + 128, ah, dVl + ks * 2, IDESC_PV, 1);
                    }
                    TCGEN05_COMMIT(smb + 224 + 16 * pb);
                }
                if (i <= 29) {
                    MBARRIER_WAIT_PARITY(smb + 128 + 16 * sb, (i >> 1) & 1);
                    if (i >= 2)
                        MBARRIER_WAIT_PARITY(smb + 224 + 16 * (i & 1), ((i - 2) >> 1) & 1);
                    LOADKV(i + 2);
                }
            }
            {
                const int j = 31, pb = 1, pj = 1;
                MBARRIER_WAIT_PARITY(smb + 192 + 16 * pb, pj);
                TCGEN05_FENCE_AFTER();
                uint32_t vst = smb + AOFF_V + (j & 3) * 32768;
                uint64_t dVh = MAKE_SMEM_DESC(vst);
                uint64_t dVl = MAKE_SMEM_DESC(vst + 16384);
#pragma unroll
                for (int ks = 0; ks < 4; ++ks) {
                    uint32_t ah = tmem + 256 + pb * 64 + ks * 8;
                    uint32_t al = tmem + 288 + pb * 64 + ks * 8;
                    mma_f16_ts(tmem + 128, ah, dVh + ks * 2, IDESC_PV, 1);
                    mma_f16_ts(tmem + 128, al, dVh + ks * 2, IDESC_PV, 1);
                    mma_f16_ts(tmem + 128, ah, dVl + ks * 2, IDESC_PV, 1);
                }
                TCGEN05_COMMIT(smb + 224 + 16 * pb);
                MBARRIER_WAIT_PARITY(smb + 224 + 16 * pb, pj);
            }
#undef LOADKV
        }
    }

    // ---------------- softmax warps (8) ----------------
    if (wid < 8) {
        const int sub = wid & 3;
        const int hw  = wid >> 2;
        const uint32_t wo = (uint32_t)sub << 21;
        float l = 0.0f;

        if (wid < 4) {
            MBARRIER_WAIT_PARITY(smb + 64, 0);
            const int r = sub * 32 + lid;
#pragma unroll
            for (int part = 0; part < 4; ++part) {
                uint32_t base = AOFF_QS + (part >> 1) * 32768 + (part & 1) * 16384;
                uint32_t q32[32];
#pragma unroll
                for (int g = 0; g < 8; ++g) {
                    uint32_t off = base + SMEM_SWIZZLE_128B((uint32_t)(r * 128 + g * 16));
                    uint4 v = *(const uint4*)(sm + off);
                    q32[g * 4 + 0] = v.x; q32[g * 4 + 1] = v.y;
                    q32[g * 4 + 2] = v.z; q32[g * 4 + 3] = v.w;
                }
                uint32_t dst = tmem + 384 + (part >> 1) * 64 + (part & 1) * 32 + wo;
                TCGEN05_ST_32X32B_X32(dst, q32);
            }
            TCGEN05_WAIT_ST();
            TCGEN05_FENCE_BEFORE();
            if (elect_one_pred()) MBARRIER_ARRIVE(smb + 80);
        }

        const float* md_base = (const float*)(sm + AOFF_MASK);
        for (int i = 0; i < 32; ++i) {
            int s = i & 1, ph = (i >> 1) & 1;
            MBARRIER_WAIT_PARITY(smb + 128 + 16 * s, ph);
            TCGEN05_FENCE_AFTER();
            uint32_t r0[32];
            TCGEN05_LD_32X32B_X32(r0, tmem + s * 64 + hw * 32);
            TCGEN05_WAIT_LD();
            if (elect_one_pred()) MBARRIER_ARRIVE(smb + 160 + 16 * s);

            const float* md = md_base + i * 64 + hw * 32;
#pragma unroll
            for (int j = 0; j < 32; ++j) {
                float e = __expf(__uint_as_float(r0[j]) + md[j]);
                l += e;
                r0[j] = __float_as_uint(e);
            }
            uint32_t phv[16], plv[16];
#pragma unroll
            for (int p = 0; p < 16; ++p) {
                __nv_bfloat16 h0, h1, l0, l1;
                split_bf16(__uint_as_float(r0[2 * p]), h0, l0);
                split_bf16(__uint_as_float(r0[2 * p + 1]), h1, l1);
                __nv_bfloat162 hp(h0, h1), lp(l0, l1);
                phv[p] = *(uint32_t*)&hp;
                plv[p] = *(uint32_t*)&lp;
            }
            TCGEN05_ST_32X32B_X16(tmem + 256 + s * 64 + hw * 16 + wo, phv);
            TCGEN05_ST_32X32B_X16(tmem + 288 + s * 64 + hw * 16 + wo, plv);
            TCGEN05_WAIT_ST();
            TCGEN05_FENCE_BEFORE();
            if (elect_one_pred()) MBARRIER_ARRIVE(smb + 192 + 16 * s);
        }
        ((float*)(sm + AOFF_LBUF))[hw * 128 + sub * 32 + lid] = l;
    }

    __syncthreads();

    if (wid < 8) {
        TCGEN05_FENCE_AFTER();
        const int sub = wid & 3;
        const int hw = wid >> 2;
        const uint32_t wo = (uint32_t)sub << 21;
        const int row = sub * 32 + lid;
        const float* lbuf = (const float*)(sm + AOFF_LBUF);
        float inv = 1.0f / (lbuf[row] + lbuf[128 + row]);
        int qrow = rt * 128 + row;
        int tok = b * 2048 + qrow;
        int rtt = tok >> 7, rr = tok & 127;
        int hh = bh & 15;
        __align__(16) __nv_bfloat16 hv[8], lv[8];
#pragma unroll
        for (int t = 0; t < 2; ++t) {
            int cb = hw * 2 + t;
            uint32_t r[32];
            TCGEN05_LD_32X32B_X32(r, tmem + 128 + cb * 32 + wo);
            TCGEN05_WAIT_LD();
            int c_ = hh * 2 + (cb >> 1);
            size_t tb = ((size_t)(c_ * NRT_A + rtt)) << 14;
            int kcb = (cb & 1) * 32;
#pragma unroll
            for (int j0 = 0; j0 < 32; j0 += 8) {
#pragma unroll
                for (int j = 0; j < 8; ++j)
                    split_bf16(__uint_as_float(r[j0 + j]) * inv, hv[j], lv[j]);
                uint32_t so = SMEM_SWIZZLE_128B((uint32_t)(rr * 128 + (kcb + j0) * 2));
                *(uint4*)((char*)g_chh + tb + so) = *(uint4*)hv;
                *(uint4*)((char*)g_cll + tb + so) = *(uint4*)lv;
            }
        }
        TCGEN05_FENCE_BEFORE();
    }

    __syncthreads();
    if (tid == 0) {
        MBARRIER_INVAL(smb + 64);
        MBARRIER_INVAL(smb + 80);
#pragma unroll
        for (int s = 0; s < 2; ++s) {
            MBARRIER_INVAL(smb + 96 + 16 * s);
            MBARRIER_INVAL(smb + 128 + 16 * s);
            MBARRIER_INVAL(smb + 160 + 16 * s);
            MBARRIER_INVAL(smb + 192 + 16 * s);
            MBARRIER_INVAL(smb + 224 + 16 * s);
        }
    }
    __syncthreads();
    if (wid == 0) {
        TCGEN05_RELINQUISH();
        TCGEN05_DEALLOC(tmem, 512);
    }
#endif  // HAS_TCGEN05
}

// ============================================================
extern "C" void kernel_launch(void* const* d_in, const int* in_sizes, int n_in,
                              void* d_out, int out_size)
{
    const float* x    = (const float*)d_in[0];
    const float* mask = (const float*)d_in[1];
    const float* Wq   = (const float*)d_in[2];
    const float* bq   = (const float*)d_in[3];
    const float* Wk   = (const float*)d_in[4];
    const float* bk   = (const float*)d_in[5];
    const float* Wv   = (const float*)d_in[6];
    const float* bv   = (const float*)d_in[7];
    const float* Wo   = (const float*)d_in[8];
    const float* bo   = (const float*)d_in[9];
    float* out = (float*)d_out;

    const int XN = M_TOK * D_MODEL;
    const int TOTAL8 = XN8 + 4 * WN8;

    cudaFuncSetAttribute(gemm_tc, cudaFuncAttributeMaxDynamicSharedMemorySize, GEMM_SMEM);
    cudaFuncSetAttribute(attn_tc, cudaFuncAttributeMaxDynamicSharedMemorySize, ATTN_SMEM);

    split_all<<<TOTAL8 / 256, 256>>>(x, Wq, Wk, Wv, Wo);
    // grid: x = 2 col-block-pairs dim (8 blocks x 2 ranks), y = 16 row-tile pairs
    gemm_tc<<<dim3(16, 16, 3), 256, GEMM_SMEM>>>(0, bq, bk, bv, bo, out);
    pack_v<<<XN / 8 / 256, 256>>>();
    attn_tc<<<dim3(16, 32), 288, ATTN_SMEM>>>(mask);
    gemm_tc<<<dim3(16, 16, 1), 256, GEMM_SMEM>>>(3, bq, bk, bv, bo, out);
}

// round 14
// speedup vs baseline: 1.0569x; 1.0569x over previous
#include <cuda_runtime.h>
#include <cuda_bf16.h>
#include <cstdint>

#define D_MODEL 2048
#define SEQ     2048
#define BATCH   2
#define NHEADS  16
#define HDIM    128
#define M_TOK   (BATCH*SEQ)   // 4096

#if defined(__CUDA_ARCH_FEAT_SM103_ALL) || defined(__CUDA_ARCH_FEAT_SM100_ALL) || \
    (defined(__CUDA_ARCH_SPECIFIC__) && (__CUDA_ARCH_SPECIFIC__ >= 1000))
#define HAS_TCGEN05 1
#else
#define HAS_TCGEN05 0
#endif

// ---- persistent scratch ----
__device__ float g_v[M_TOK * D_MODEL];     // fp32 V (packed to V^T by pack_v)

// GEMM operands: 8KB tiles (128 rows x 32 k, 64B rows, SW64), tile idx (c32*nrt + rt)
__device__ __nv_bfloat16 g_xh[M_TOK * D_MODEL];
__device__ __nv_bfloat16 g_xl[M_TOK * D_MODEL];
__device__ __nv_bfloat16 g_chh[M_TOK * D_MODEL];   // packed ctx (written by attn)
__device__ __nv_bfloat16 g_cll[M_TOK * D_MODEL];
__device__ __nv_bfloat16 g_wh[4][D_MODEL * D_MODEL];
__device__ __nv_bfloat16 g_wl[4][D_MODEL * D_MODEL];

// attention operands (SW128 128B-row formats, unchanged)
__device__ __nv_bfloat16 g_aqh[M_TOK * D_MODEL];   // Q tiles: [bh][rt16][2ch x 16KB]
__device__ __nv_bfloat16 g_aql[M_TOK * D_MODEL];
__device__ __nv_bfloat16 g_akh[M_TOK * D_MODEL];   // K tiles: [bh][kt32][2ch x 8KB]
__device__ __nv_bfloat16 g_akl[M_TOK * D_MODEL];
__device__ __nv_bfloat16 g_avh[M_TOK * D_MODEL];   // V^T tiles: [bh][kt32][16KB]
__device__ __nv_bfloat16 g_avl[M_TOK * D_MODEL];

// ============================================================
// PTX helpers
// ============================================================
__device__ __forceinline__ uint32_t smem_u32(const void* p) {
    uint32_t a;
    asm("{ .reg .u64 t; cvta.to.shared.u64 t, %1; cvt.u32.u64 %0, t; }" : "=r"(a) : "l"(p));
    return a;
}
__device__ __forceinline__ uint32_t elect_one_pred() {
    uint32_t p;
    asm volatile("{ .reg .pred p; elect.sync _|p, 0xFFFFFFFF; selp.b32 %0, 1, 0, p; }" : "=r"(p));
    return p;
}
static constexpr uint64_t SMEM_DESC_BASE_SW128 =
    (uint64_t(2) << 61) | (uint64_t(1) << 46) | (uint64_t(64) << 32) | (uint64_t(1) << 16);
static constexpr uint64_t SMEM_DESC_BASE_SW64 =
    (uint64_t(4) << 61) | (uint64_t(1) << 46) | (uint64_t(32) << 32) | (uint64_t(1) << 16);
#define MAKE_SMEM_DESC(base_addr) \
    (SMEM_DESC_BASE_SW128 | ((uint64_t)((base_addr) >> 4) & 0x3FFF))
#define MAKE_SMEM_DESC_SW64(base_addr) \
    (SMEM_DESC_BASE_SW64 | ((uint64_t)((base_addr) >> 4) & 0x3FFF))
#define SMEM_SWIZZLE_128B(off) ((off) ^ (((off) >> 3) & 0x70))
#define SMEM_SWIZZLE_64B(off)  ((off) ^ (((off) >> 3) & 0x30))

#define MBARRIER_INIT(mbar, count) \
    asm volatile("mbarrier.init.shared.b64 [%0], %1;" \
                 :: "r"((uint32_t)(mbar)), "r"((uint32_t)(count)) : "memory")
#define MBARRIER_INVAL(mbar) \
    asm volatile("mbarrier.inval.shared.b64 [%0];" :: "r"((uint32_t)(mbar)) : "memory")
#define MBARRIER_EXPECT_TX(mbar, bytes) \
    asm volatile("mbarrier.arrive.expect_tx.shared.b64 _, [%0], %1;" \
                 :: "r"((uint32_t)(mbar)), "r"((uint32_t)(bytes)) : "memory")
#define MBARRIER_ARRIVE(mbar) \
    asm volatile("mbarrier.arrive.shared.b64 _, [%0];" :: "r"((uint32_t)(mbar)) : "memory")
#define MBARRIER_WAIT_PARITY(mbar, parity) do {                                          \
    uint32_t _m = (uint32_t)(mbar);                                                      \
    uint32_t _p = (uint32_t)(parity);                                                    \
    uint32_t _done;                                                                      \
    asm volatile("{ .reg .pred p; mbarrier.try_wait.parity.acquire.cta.shared::cta.b64 " \
                 "p, [%1], %2; selp.b32 %0, 1, 0, p; }"                                  \
                 : "=r"(_done) : "r"(_m), "r"(_p) : "memory");                           \
    if (!_done) {                                                                        \
        asm volatile("{ .reg .pred P1; WL_%=: "                                          \
                     "mbarrier.try_wait.parity.acquire.cta.shared::cta.b64 P1, [%0], %1, 0x989680; " \
                     "@P1 bra.uni WD_%=; bra.uni WL_%=; WD_%=: }"                        \
                     :: "r"(_m), "r"(_p) : "memory");                                    \
    }                                                                                    \
} while (0)

#define BULK_CP(dst_smem, src_gmem, bytes, mbar) \
    asm volatile("cp.async.bulk.shared::cluster.global.mbarrier::complete_tx::bytes " \
                 "[%0], [%1], %2, [%3];" \
                 :: "r"((uint32_t)(dst_smem)), "l"(src_gmem), "r"((uint32_t)(bytes)), \
                    "r"((uint32_t)(mbar)) : "memory")

#if HAS_TCGEN05
#define TCGEN05_ALLOC(smem_addr, nCols) \
    asm volatile("tcgen05.alloc.cta_group::1.sync.aligned.shared::cta.b32 [%0], %1;" \
                 :: "r"((uint32_t)(smem_addr)), "r"((uint32_t)(nCols)) : "memory")
#define TCGEN05_DEALLOC(tmem_addr, nCols) \
    asm volatile("tcgen05.dealloc.cta_group::1.sync.aligned.b32 %0, %1;" \
                 :: "r"(tmem_addr), "r"((uint32_t)(nCols)))
#define TCGEN05_RELINQUISH() \
    asm volatile("tcgen05.relinquish_alloc_permit.cta_group::1.sync.aligned;")
#define TCGEN05_COMMIT(mbar) \
    asm volatile("tcgen05.commit.cta_group::1.mbarrier::arrive::one.shared::cluster.b64 [%0];" \
                 :: "r"((uint32_t)(mbar)) : "memory")
#define TCGEN05_FENCE_AFTER() \
    asm volatile("tcgen05.fence::after_thread_sync;" ::: "memory")
#define TCGEN05_FENCE_BEFORE() \
    asm volatile("tcgen05.fence::before_thread_sync;" ::: "memory")
#define TCGEN05_WAIT_LD() \
    asm volatile("tcgen05.wait::ld.sync.aligned;" ::: "memory")
#define TCGEN05_WAIT_ST() \
    asm volatile("tcgen05.wait::st.sync.aligned;" ::: "memory")

#define TCGEN05_LD_32X32B_X32(r, tmem_addr) \
    asm volatile( \
        "tcgen05.ld.sync.aligned.32x32b.x32.b32 " \
        "{%0, %1, %2, %3, %4, %5, %6, %7, " \
        " %8, %9, %10, %11, %12, %13, %14, %15, " \
        " %16, %17, %18, %19, %20, %21, %22, %23, " \
        " %24, %25, %26, %27, %28, %29, %30, %31}, [%32];" \
        : "=r"((r)[0]),  "=r"((r)[1]),  "=r"((r)[2]),  "=r"((r)[3]), \
          "=r"((r)[4]),  "=r"((r)[5]),  "=r"((r)[6]),  "=r"((r)[7]), \
          "=r"((r)[8]),  "=r"((r)[9]),  "=r"((r)[10]), "=r"((r)[11]), \
          "=r"((r)[12]), "=r"((r)[13]), "=r"((r)[14]), "=r"((r)[15]), \
          "=r"((r)[16]), "=r"((r)[17]), "=r"((r)[18]), "=r"((r)[19]), \
          "=r"((r)[20]), "=r"((r)[21]), "=r"((r)[22]), "=r"((r)[23]), \
          "=r"((r)[24]), "=r"((r)[25]), "=r"((r)[26]), "=r"((r)[27]), \
          "=r"((r)[28]), "=r"((r)[29]), "=r"((r)[30]), "=r"((r)[31]) \
        : "r"(tmem_addr))

#define TCGEN05_ST_32X32B_X32(tmem_addr, r) \
    asm volatile( \
        "tcgen05.st.sync.aligned.32x32b.x32.b32 [%0], " \
        "{%1, %2, %3, %4, %5, %6, %7, %8, " \
        " %9, %10, %11, %12, %13, %14, %15, %16, " \
        " %17, %18, %19, %20, %21, %22, %23, %24, " \
        " %25, %26, %27, %28, %29, %30, %31, %32};" \
        :: "r"(tmem_addr), \
           "r"((r)[0]),  "r"((r)[1]),  "r"((r)[2]),  "r"((r)[3]), \
           "r"((r)[4]),  "r"((r)[5]),  "r"((r)[6]),  "r"((r)[7]), \
           "r"((r)[8]),  "r"((r)[9]),  "r"((r)[10]), "r"((r)[11]), \
           "r"((r)[12]), "r"((r)[13]), "r"((r)[14]), "r"((r)[15]), \
           "r"((r)[16]), "r"((r)[17]), "r"((r)[18]), "r"((r)[19]), \
           "r"((r)[20]), "r"((r)[21]), "r"((r)[22]), "r"((r)[23]), \
           "r"((r)[24]), "r"((r)[25]), "r"((r)[26]), "r"((r)[27]), \
           "r"((r)[28]), "r"((r)[29]), "r"((r)[30]), "r"((r)[31]) \
        : "memory")

#define TCGEN05_ST_32X32B_X16(tmem_addr, r) \
    asm volatile( \
        "tcgen05.st.sync.aligned.32x32b.x16.b32 [%0], " \
        "{%1, %2, %3, %4, %5, %6, %7, %8, " \
        " %9, %10, %11, %12, %13, %14, %15, %16};" \
        :: "r"(tmem_addr), \
           "r"((r)[0]),  "r"((r)[1]),  "r"((r)[2]),  "r"((r)[3]), \
           "r"((r)[4]),  "r"((r)[5]),  "r"((r)[6]),  "r"((r)[7]), \
           "r"((r)[8]),  "r"((r)[9]),  "r"((r)[10]), "r"((r)[11]), \
           "r"((r)[12]), "r"((r)[13]), "r"((r)[14]), "r"((r)[15]) \
        : "memory")

__device__ __forceinline__ void mma_f16_ss(uint32_t d_tmem, uint64_t a_desc, uint64_t b_desc,
                                           uint32_t idesc, uint32_t enable) {
    asm volatile(
        "{\n\t"
        ".reg .pred p;\n\t"
        "setp.ne.u32 p, %4, 0;\n\t"
        "tcgen05.mma.cta_group::1.kind::f16 [%0], %1, %2, %3, {%5, %5, %5, %5}, p;\n\t"
        "}"
        :: "r"(d_tmem), "l"(a_desc), "l"(b_desc), "r"(idesc), "r"(enable), "r"(0u)
        : "memory");
}
__device__ __forceinline__ void mma_f16_ts(uint32_t d_tmem, uint32_t a_tmem, uint64_t b_desc,
                                           uint32_t idesc, uint32_t enable) {
    asm volatile(
        "{\n\t"
        ".reg .pred p;\n\t"
        "setp.ne.u32 p, %4, 0;\n\t"
        "tcgen05.mma.cta_group::1.kind::f16 [%0], [%1], %2, %3, {%5, %5, %5, %5}, p;\n\t"
        "}"
        :: "r"(d_tmem), "r"(a_tmem), "l"(b_desc), "r"(idesc), "r"(enable), "r"(0u)
        : "memory");
}
#endif  // HAS_TCGEN05

__device__ __forceinline__ void split_bf16(float f, __nv_bfloat16& h, __nv_bfloat16& l) {
    h = __float2bfloat16(f);
    l = __float2bfloat16(f - __bfloat162float(h));
}

// ============================================================
// Merged split+pack: x + W0..W3, NEW 8KB-tile SW64 format.
// tile(c32, rt128) at (c32*nrt + rt)*8KB; inside: SW64(r*64 + kc*2)
// ============================================================
#define XN8 (M_TOK * D_MODEL / 8)
#define WN8 (D_MODEL * D_MODEL / 8)

__global__ __launch_bounds__(256) void split_all(
    const float* __restrict__ x, const float* __restrict__ W0,
    const float* __restrict__ W1, const float* __restrict__ W2,
    const float* __restrict__ W3)
{
    int i = blockIdx.x * blockDim.x + threadIdx.x;
    const float* src;
    __nv_bfloat16 *hi, *lo;
    int nrt, li;
    if (i < XN8) {
        src = x; hi = g_xh; lo = g_xl; nrt = 32; li = i;
    } else {
        int w = (i - XN8) >> 19;
        li = (i - XN8) & (WN8 - 1);
        src = (w == 0) ? W0 : (w == 1) ? W1 : (w == 2) ? W2 : W3;
        hi = g_wh[w]; lo = g_wl[w]; nrt = 16;
    }
    int elem = li * 8;
    int row = elem >> 11;
    int col = elem & 2047;
    int rt = row >> 7, r = row & 127;
    int c  = col >> 5, kc = col & 31;
    size_t tb = ((size_t)(c * nrt + rt)) << 13;
    uint32_t so = SMEM_SWIZZLE_64B((uint32_t)(r * 64 + kc * 2));

    float4 v0 = ((const float4*)src)[(size_t)li * 2];
    float4 v1 = ((const float4*)src)[(size_t)li * 2 + 1];
    float f[8] = {v0.x, v0.y, v0.z, v0.w, v1.x, v1.y, v1.z, v1.w};
    __align__(16) __nv_bfloat16 h[8], l[8];
#pragma unroll
    for (int j = 0; j < 8; j++) split_bf16(f[j], h[j], l[j]);
    *(uint4*)((char*)hi + tb + so) = *(uint4*)h;
    *(uint4*)((char*)lo + tb + so) = *(uint4*)l;
}

// ============================================================
// V^T packer (attention format, unchanged)
// ============================================================
__global__ __launch_bounds__(256) void pack_v()
{
    int i = blockIdx.x * blockDim.x + threadIdx.x;
    int elem = i * 8;
    int tok = elem >> 11, col = elem & 2047;
    int b = tok >> 11, s = tok & 2047;
    int h = col >> 7, d = col & 127;
    int bh = b * 16 + h;
    int kt = s >> 6, sc = s & 63;
    size_t tb = ((size_t)(bh * 32 + kt)) << 14;
    const float* src = g_v + (size_t)tok * 2048 + col;
    float4 v0 = *(const float4*)src, v1 = *(const float4*)(src + 4);
    float f[8] = {v0.x, v0.y, v0.z, v0.w, v1.x, v1.y, v1.z, v1.w};
#pragma unroll
    for (int j = 0; j < 8; j++) {
        __nv_bfloat16 hh, ll;
        split_bf16(f[j], hh, ll);
        uint32_t off = SMEM_SWIZZLE_128B((uint32_t)((d + j) * 128 + sc * 2));
        *(__nv_bfloat16*)((char*)g_avh + tb + off) = hh;
        *(__nv_bfloat16*)((char*)g_avl + tb + off) = ll;
    }
}

// ============================================================
// tcgen05 GEMM, single CTA computes 256(M) x 256(N):
// 2 accumulators (TMEM 0 / 256), A-pair per chunk, KCH=32 (SW64 tiles).
// Chunk = Ah-pair 16K | Al-pair 16K | Bh 16K | Bl 16K = 64KB, 3 stages.
// mode 0/1 = Q/K proj (packed epilogue), 2 = V (fp32), 3 = O (fp32 out).
// grid (8 bx, 16 row-pairs, modes). No clusters.
// ============================================================
#define NCH  64                         // 2048/32
#define TIL8 8192
#define STG  (8 * TIL8)                 // 64KB
#define SMB0 1024
#define GEMM_SMEM (SMB0 + 3 * STG)      // 197632
#define GEMM_IDESC 0x8400490u           // F32, BF16xBF16, M=128, N=256

__global__ __launch_bounds__(256) void gemm_tc(
    int mode_base, const float* __restrict__ b0, const float* __restrict__ b1,
    const float* __restrict__ b2, const float* __restrict__ b3,
    float* __restrict__ out)
{
#if HAS_TCGEN05
    extern __shared__ char sm[];
    const uint32_t smb = smem_u32(sm);
    const int tid = threadIdx.x;
    const int wid = tid >> 5;
    const int lid = tid & 31;
    const int rp = blockIdx.y;           // row-pair: rows [rp*256, rp*256+256)
    const int bx = blockIdx.x;           // 256-col block
    const int mode = mode_base + blockIdx.z;

    const __nv_bfloat16* Ah = (mode < 3) ? g_xh : g_chh;
    const __nv_bfloat16* Al = (mode < 3) ? g_xl : g_cll;
    const __nv_bfloat16* Bh = g_wh[mode];
    const __nv_bfloat16* Bl = g_wl[mode];
    const float* bias = (mode == 0) ? b0 : (mode == 1) ? b1 : (mode == 2) ? b2 : b3;
    const float alpha = (mode == 0) ? 0.08838834764831845f : 1.0f;

    if (wid == 0) TCGEN05_ALLOC(smb + 0, 512);
    if (tid == 0) {
#pragma unroll
        for (int s = 0; s < 3; ++s) {
            MBARRIER_INIT(smb + 64 + 16 * s, 1);    // full (tx)
            MBARRIER_INIT(smb + 112 + 16 * s, 1);   // mma commit
        }
    }
    __syncthreads();

    uint32_t tmem;
    asm volatile("ld.shared.b32 %0, [%1];" : "=r"(tmem) : "r"(smb + 0));

    if (wid == 0 && elect_one_pred()) {
#define LOAD_CHUNK(c, s)                                                        \
        do {                                                                    \
            uint32_t st = smb + SMB0 + (s) * STG;                               \
            uint32_t fb = smb + 64 + 16 * (s);                                  \
            size_t ao = ((size_t)((c) * 32 + 2 * rp)) << 13;                    \
            size_t bo = ((size_t)((c) * 16 + 2 * bx)) << 13;                    \
            MBARRIER_EXPECT_TX(fb, 4 * 2 * TIL8);                               \
            BULK_CP(st,             (const char*)Ah + ao, 2 * TIL8, fb);        \
            BULK_CP(st + 2 * TIL8,  (const char*)Al + ao, 2 * TIL8, fb);        \
            BULK_CP(st + 4 * TIL8,  (const char*)Bh + bo, 2 * TIL8, fb);        \
            BULK_CP(st + 6 * TIL8,  (const char*)Bl + bo, 2 * TIL8, fb);        \
        } while (0)

        LOAD_CHUNK(0, 0);
        LOAD_CHUNK(1, 1);
        LOAD_CHUNK(2, 2);

        for (int c = 0; c < NCH; ++c) {
            int s = c % 3, ph = (c / 3) & 1;
            uint32_t st = smb + SMB0 + s * STG;
            MBARRIER_WAIT_PARITY(smb + 64 + 16 * s, ph);
            uint64_t dBh = MAKE_SMEM_DESC_SW64(st + 4 * TIL8);
            uint64_t dBl = MAKE_SMEM_DESC_SW64(st + 6 * TIL8);
#pragma unroll
            for (int ks = 0; ks < 2; ++ks) {
#pragma unroll
                for (int t = 0; t < 2; ++t) {
                    uint64_t dAh = MAKE_SMEM_DESC_SW64(st + t * TIL8) + ks * 2;
                    uint64_t dAl = MAKE_SMEM_DESC_SW64(st + 2 * TIL8 + t * TIL8) + ks * 2;
                    uint32_t acc = tmem + t * 256;
                    mma_f16_ss(acc, dAh, dBh + ks * 2, GEMM_IDESC, (c | ks) != 0);
                    mma_f16_ss(acc, dAl, dBh + ks * 2, GEMM_IDESC, 1);
                    mma_f16_ss(acc, dAh, dBl + ks * 2, GEMM_IDESC, 1);
                }
            }
            TCGEN05_COMMIT(smb + 112 + 16 * s);
            if (c + 3 < NCH) {
                MBARRIER_WAIT_PARITY(smb + 112 + 16 * s, ph);
                LOAD_CHUNK(c + 3, s);
            }
        }
        MBARRIER_WAIT_PARITY(smb + 112 + 16 * ((NCH - 1) % 3), ((NCH - 1) / 3) & 1);
#undef LOAD_CHUNK
    }
    __syncthreads();
    TCGEN05_FENCE_AFTER();

    // epilogue: two accumulators (two 128-row tiles)
    const int wg = wid >> 2;
    const int sub = wid & 3;
    const int hd = bx * 2 + wg;
    __align__(16) __nv_bfloat16 hv[8], lv[8];

#pragma unroll
    for (int t = 0; t < 2; ++t) {
        const int m = (rp * 2 + t) * 128 + sub * 32 + lid;
        const int b_ = m >> 11, s_ = m & 2047;
        const int bh2 = b_ * 16 + hd;
#pragma unroll
        for (int cb = 0; cb < 4; ++cb) {
            uint32_t r[32];
            TCGEN05_LD_32X32B_X32(r, tmem + t * 256 + wg * 128 + cb * 32);
            TCGEN05_WAIT_LD();
            int n0 = bx * 256 + wg * 128 + cb * 32;

            if (mode == 3) {
                float* crow = out + (size_t)m * D_MODEL;
#pragma unroll
                for (int j = 0; j < 32; j += 4) {
                    float4 o;
                    o.x = __uint_as_float(r[j + 0]) + bias[n0 + j + 0];
                    o.y = __uint_as_float(r[j + 1]) + bias[n0 + j + 1];
                    o.z = __uint_as_float(r[j + 2]) + bias[n0 + j + 2];
                    o.w = __uint_as_float(r[j + 3]) + bias[n0 + j + 3];
                    *(float4*)(crow + n0 + j) = o;
                }
            } else if (mode == 2) {
                float* crow = g_v + (size_t)m * D_MODEL;
#pragma unroll
                for (int j = 0; j < 32; j += 4) {
                    float4 o;
                    o.x = __uint_as_float(r[j + 0]) + bias[n0 + j + 0];
                    o.y = __uint_as_float(r[j + 1]) + bias[n0 + j + 1];
                    o.z = __uint_as_float(r[j + 2]) + bias[n0 + j + 2];
                    o.w = __uint_as_float(r[j + 3]) + bias[n0 + j + 3];
                    *(float4*)(crow + n0 + j) = o;
                }
            } else {
                // packed attention operand epilogue (Q: mode 0, K: mode 1) — SW128 formats
                size_t tb;
                uint32_t rr;
                char *dh, *dl;
                if (mode == 0) {
                    int rt2 = s_ >> 7; rr = s_ & 127;
                    tb = ((size_t)((bh2 * 16 + rt2) * 2 + (cb >> 1))) << 14;
                    dh = (char*)g_aqh + tb; dl = (char*)g_aql + tb;
                } else {
                    int kt = s_ >> 6; rr = s_ & 63;
                    tb = ((size_t)((bh2 * 32 + kt) * 2 + (cb >> 1))) << 13;
                    dh = (char*)g_akh + tb; dl = (char*)g_akl + tb;
                }
                int kcb = (cb & 1) * 32;
#pragma unroll
                for (int j0 = 0; j0 < 32; j0 += 8) {
#pragma unroll
                    for (int j = 0; j < 8; ++j) {
                        float f = (__uint_as_float(r[j0 + j]) + bias[n0 + j0 + j]) * alpha;
                        split_bf16(f, hv[j], lv[j]);
                    }
                    uint32_t so = SMEM_SWIZZLE_128B((uint32_t)(rr * 128 + (kcb + j0) * 2));
                    *(uint4*)(dh + so) = *(uint4*)hv;
                    *(uint4*)(dl + so) = *(uint4*)lv;
                }
            }
        }
    }
    TCGEN05_FENCE_BEFORE();

    __syncthreads();
    if (tid == 0) {
#pragma unroll
        for (int s = 0; s < 3; ++s) {
            MBARRIER_INVAL(smb + 64 + 16 * s);
            MBARRIER_INVAL(smb + 112 + 16 * s);
        }
    }
    __syncthreads();
    if (wid == 0) {
        TCGEN05_RELINQUISH();
        TCGEN05_DEALLOC(tmem, 512);
    }
#endif
}

// ============================================================
// tcgen05 flash attention (R11 8-warp version) + SW64 ctx epilogue
// ============================================================
#define AOFF_LBUF 1024
#define AOFF_MASK 2048
#define AOFF_K    10240
#define AOFF_V    75776
#define AOFF_QS   (AOFF_V + 65536)
#define ATTN_SMEM 206848
#define IDESC_S   0x8100490u
#define IDESC_PV  0x8200490u

__global__ __launch_bounds__(288) void attn_tc(const float* __restrict__ mask)
{
#if HAS_TCGEN05
    extern __shared__ char sm[];
    const uint32_t smb = smem_u32(sm);
    const int tid = threadIdx.x;
    const int wid = tid >> 5;
    const int lid = tid & 31;
    const int rt = blockIdx.x;
    const int bh = blockIdx.y;
    const int b = bh >> 4;

    if (wid == 0) TCGEN05_ALLOC(smb + 0, 512);
    if (tid == 0) {
        MBARRIER_INIT(smb + 64, 1);    // qbar (tx)
        MBARRIER_INIT(smb + 80, 4);    // qdone
#pragma unroll
        for (int s = 0; s < 2; ++s) {
            MBARRIER_INIT(smb + 96 + 16 * s, 1);    // full (tx)
            MBARRIER_INIT(smb + 128 + 16 * s, 1);   // s_full (commit)
            MBARRIER_INIT(smb + 160 + 16 * s, 8);   // smax_free
            MBARRIER_INIT(smb + 192 + 16 * s, 8);   // p_ready
            MBARRIER_INIT(smb + 224 + 16 * s, 1);   // pv_done (commit)
        }
    }
    for (int j = tid; j < SEQ; j += 288) {
        float mv = mask[b * SEQ + j];
        ((float*)(sm + AOFF_MASK))[j] = (1.0f - mv) * -1e30f;
    }
    __syncthreads();

    uint32_t tmem;
    asm volatile("ld.shared.b32 %0, [%1];" : "=r"(tmem) : "r"(smb + 0));

    // ---------------- control warp ----------------
    if (wid == 8) {
        if (elect_one_pred()) {
#define LOADKV(c)                                                          \
            do {                                                           \
                size_t kb = ((size_t)(bh * 32 + (c))) << 14;               \
                uint32_t kst = smb + AOFF_K + ((c) & 1) * 32768;           \
                uint32_t vst = smb + AOFF_V + ((c) & 3) * 32768;           \
                uint32_t fb = smb + 96 + 16 * ((c) & 1);                   \
                MBARRIER_EXPECT_TX(fb, 65536);                             \
                BULK_CP(kst,         (const char*)g_akh + kb, 16384, fb);  \
                BULK_CP(kst + 16384, (const char*)g_akl + kb, 16384, fb);  \
                BULK_CP(vst,         (const char*)g_avh + kb, 16384, fb);  \
                BULK_CP(vst + 16384, (const char*)g_avl + kb, 16384, fb);  \
            } while (0)

            {
                size_t qb = ((size_t)(bh * 16 + rt)) << 15;
                MBARRIER_EXPECT_TX(smb + 64, 65536);
                BULK_CP(smb + AOFF_QS,         (const char*)g_aqh + qb, 32768, smb + 64);
                BULK_CP(smb + AOFF_QS + 32768, (const char*)g_aql + qb, 32768, smb + 64);
                LOADKV(0);
                LOADKV(1);
            }
            MBARRIER_WAIT_PARITY(smb + 80, 0);
            TCGEN05_FENCE_AFTER();

            const uint32_t qh = tmem + 384, ql = tmem + 448;

            for (int i = 0; i < 32; ++i) {
                const int sb = i & 1;
                MBARRIER_WAIT_PARITY(smb + 96 + 16 * sb, (i >> 1) & 1);
                if (i >= 2) MBARRIER_WAIT_PARITY(smb + 160 + 16 * sb, ((i - 2) >> 1) & 1);
                {
                    uint32_t kst = smb + AOFF_K + sb * 32768;
                    uint32_t sreg = tmem + sb * 64;
#pragma unroll
                    for (int st = 0; st < 8; ++st) {
                        uint64_t bh_ = MAKE_SMEM_DESC(kst + (st >> 2) * 8192) + (st & 3) * 2;
                        uint64_t bl_ = MAKE_SMEM_DESC(kst + 16384 + (st >> 2) * 8192) + (st & 3) * 2;
                        mma_f16_ts(sreg, qh + st * 8, bh_, IDESC_S, st != 0);
                        mma_f16_ts(sreg, ql + st * 8, bh_, IDESC_S, 1);
                        mma_f16_ts(sreg, qh + st * 8, bl_, IDESC_S, 1);
                    }
                    TCGEN05_COMMIT(smb + 128 + 16 * sb);
                }
                if (i >= 1) {
                    const int j = i - 1, pb = j & 1, pj = (j >> 1) & 1;
                    MBARRIER_WAIT_PARITY(smb + 192 + 16 * pb, pj);
                    TCGEN05_FENCE_AFTER();
                    uint32_t vst = smb + AOFF_V + (j & 3) * 32768;
                    uint64_t dVh = MAKE_SMEM_DESC(vst);
                    uint64_t dVl = MAKE_SMEM_DESC(vst + 16384);
#pragma unroll
                    for (int ks = 0; ks < 4; ++ks) {
                        uint32_t ah = tmem + 256 + pb * 64 + ks * 8;
                        uint32_t al = tmem + 288 + pb * 64 + ks * 8;
                        mma_f16_ts(tmem + 128, ah, dVh + ks * 2, IDESC_PV, (j | ks) != 0);
                        mma_f16_ts(tmem + 128, al, dVh + ks * 2, IDESC_PV, 1);
                        mma_f16_ts(tmem + 128, ah, dVl + ks * 2, IDESC_PV, 1);
                    }
                    TCGEN05_COMMIT(smb + 224 + 16 * pb);
                }
                if (i <= 29) {
                    MBARRIER_WAIT_PARITY(smb + 128 + 16 * sb, (i >> 1) & 1);
                    if (i >= 2)
                        MBARRIER_WAIT_PARITY(smb + 224 + 16 * (i & 1), ((i - 2) >> 1) & 1);
                    LOADKV(i + 2);
                }
            }
            {
                const int j = 31, pb = 1, pj = 1;
                MBARRIER_WAIT_PARITY(smb + 192 + 16 * pb, pj);
                TCGEN05_FENCE_AFTER();
                uint32_t vst = smb + AOFF_V + (j & 3) * 32768;
                uint64_t dVh = MAKE_SMEM_DESC(vst);
                uint64_t dVl = MAKE_SMEM_DESC(vst + 16384);
#pragma unroll
                for (int ks = 0; ks < 4; ++ks) {
                    uint32_t ah = tmem + 256 + pb * 64 + ks * 8;
                    uint32_t al = tmem + 288 + pb * 64 + ks * 8;
                    mma_f16_ts(tmem + 128, ah, dVh + ks * 2, IDESC_PV, 1);
                    mma_f16_ts(tmem + 128, al, dVh + ks * 2, IDESC_PV, 1);
                    mma_f16_ts(tmem + 128, ah, dVl + ks * 2, IDESC_PV, 1);
                }
                TCGEN05_COMMIT(smb + 224 + 16 * pb);
                MBARRIER_WAIT_PARITY(smb + 224 + 16 * pb, pj);
            }
#undef LOADKV
        }
    }

    // ---------------- softmax warps (8) ----------------
    if (wid < 8) {
        const int sub = wid & 3;
        const int hw  = wid >> 2;
        const uint32_t wo = (uint32_t)sub << 21;
        float l = 0.0f;

        if (wid < 4) {
            MBARRIER_WAIT_PARITY(smb + 64, 0);
            const int r = sub * 32 + lid;
#pragma unroll
            for (int part = 0; part < 4; ++part) {
                uint32_t base = AOFF_QS + (part >> 1) * 32768 + (part & 1) * 16384;
                uint32_t q32[32];
#pragma unroll
                for (int g = 0; g < 8; ++g) {
                    uint32_t off = base + SMEM_SWIZZLE_128B((uint32_t)(r * 128 + g * 16));
                    uint4 v = *(const uint4*)(sm + off);
                    q32[g * 4 + 0] = v.x; q32[g * 4 + 1] = v.y;
                    q32[g * 4 + 2] = v.z; q32[g * 4 + 3] = v.w;
                }
                uint32_t dst = tmem + 384 + (part >> 1) * 64 + (part & 1) * 32 + wo;
                TCGEN05_ST_32X32B_X32(dst, q32);
            }
            TCGEN05_WAIT_ST();
            TCGEN05_FENCE_BEFORE();
            if (elect_one_pred()) MBARRIER_ARRIVE(smb + 80);
        }

        const float* md_base = (const float*)(sm + AOFF_MASK);
        for (int i = 0; i < 32; ++i) {
            int s = i & 1, ph = (i >> 1) & 1;
            MBARRIER_WAIT_PARITY(smb + 128 + 16 * s, ph);
            TCGEN05_FENCE_AFTER();
            uint32_t r0[32];
            TCGEN05_LD_32X32B_X32(r0, tmem + s * 64 + hw * 32);
            TCGEN05_WAIT_LD();
            if (elect_one_pred()) MBARRIER_ARRIVE(smb + 160 + 16 * s);

            const float* md = md_base + i * 64 + hw * 32;
#pragma unroll
            for (int j = 0; j < 32; ++j) {
                float e = __expf(__uint_as_float(r0[j]) + md[j]);
                l += e;
                r0[j] = __float_as_uint(e);
            }
            uint32_t phv[16], plv[16];
#pragma unroll
            for (int p = 0; p < 16; ++p) {
                __nv_bfloat16 h0, h1, l0, l1;
                split_bf16(__uint_as_float(r0[2 * p]), h0, l0);
                split_bf16(__uint_as_float(r0[2 * p + 1]), h1, l1);
                __nv_bfloat162 hp(h0, h1), lp(l0, l1);
                phv[p] = *(uint32_t*)&hp;
                plv[p] = *(uint32_t*)&lp;
            }
            TCGEN05_ST_32X32B_X16(tmem + 256 + s * 64 + hw * 16 + wo, phv);
            TCGEN05_ST_32X32B_X16(tmem + 288 + s * 64 + hw * 16 + wo, plv);
            TCGEN05_WAIT_ST();
            TCGEN05_FENCE_BEFORE();
            if (elect_one_pred()) MBARRIER_ARRIVE(smb + 192 + 16 * s);
        }
        ((float*)(sm + AOFF_LBUF))[hw * 128 + sub * 32 + lid] = l;
    }

    __syncthreads();

    // epilogue: normalize O; write ctx in NEW 8KB-tile SW64 GEMM format
    if (wid < 8) {
        TCGEN05_FENCE_AFTER();
        const int sub = wid & 3;
        const int hw = wid >> 2;
        const uint32_t wo = (uint32_t)sub << 21;
        const int row = sub * 32 + lid;
        const float* lbuf = (const float*)(sm + AOFF_LBUF);
        float inv = 1.0f / (lbuf[row] + lbuf[128 + row]);
        int qrow = rt * 128 + row;
        int tok = b * 2048 + qrow;
        int rtt = tok >> 7, rr = tok & 127;
        int hh = bh & 15;
        __align__(16) __nv_bfloat16 hv[8], lv[8];
#pragma unroll
        for (int t = 0; t < 2; ++t) {
            int cb = hw * 2 + t;
            uint32_t r[32];
            TCGEN05_LD_32X32B_X32(r, tmem + 128 + cb * 32 + wo);
            TCGEN05_WAIT_LD();
            int c32 = hh * 4 + cb;                       // k-tile (32 cols)
            size_t tb = ((size_t)(c32 * 32 + rtt)) << 13;
#pragma unroll
            for (int j0 = 0; j0 < 32; j0 += 8) {
#pragma unroll
                for (int j = 0; j < 8; ++j)
                    split_bf16(__uint_as_float(r[j0 + j]) * inv, hv[j], lv[j]);
                uint32_t so = SMEM_SWIZZLE_64B((uint32_t)(rr * 64 + j0 * 2));
                *(uint4*)((char*)g_chh + tb + so) = *(uint4*)hv;
                *(uint4*)((char*)g_cll + tb + so) = *(uint4*)lv;
            }
        }
        TCGEN05_FENCE_BEFORE();
    }

    __syncthreads();
    if (tid == 0) {
        MBARRIER_INVAL(smb + 64);
        MBARRIER_INVAL(smb + 80);
#pragma unroll
        for (int s = 0; s < 2; ++s) {
            MBARRIER_INVAL(smb + 96 + 16 * s);
            MBARRIER_INVAL(smb + 128 + 16 * s);
            MBARRIER_INVAL(smb + 160 + 16 * s);
            MBARRIER_INVAL(smb + 192 + 16 * s);
            MBARRIER_INVAL(smb + 224 + 16 * s);
        }
    }
    __syncthreads();
    if (wid == 0) {
        TCGEN05_RELINQUISH();
        TCGEN05_DEALLOC(tmem, 512);
    }
#endif  // HAS_TCGEN05
}

// ============================================================
extern "C" void kernel_launch(void* const* d_in, const int* in_sizes, int n_in,
                              void* d_out, int out_size)
{
    const float* x    = (const float*)d_in[0];
    const float* mask = (const float*)d_in[1];
    const float* Wq   = (const float*)d_in[2];
    const float* bq   = (const float*)d_in[3];
    const float* Wk   = (const float*)d_in[4];
    const float* bk   = (const float*)d_in[5];
    const float* Wv   = (const float*)d_in[6];
    const float* bv   = (const float*)d_in[7];
    const float* Wo   = (const float*)d_in[8];
    const float* bo   = (const float*)d_in[9];
    float* out = (float*)d_out;

    const int XN = M_TOK * D_MODEL;
    const int TOTAL8 = XN8 + 4 * WN8;

    cudaFuncSetAttribute(gemm_tc, cudaFuncAttributeMaxDynamicSharedMemorySize, GEMM_SMEM);
    cudaFuncSetAttribute(attn_tc, cudaFuncAttributeMaxDynamicSharedMemorySize, ATTN_SMEM);

    split_all<<<TOTAL8 / 256, 256>>>(x, Wq, Wk, Wv, Wo);
    gemm_tc<<<dim3(8, 16, 3), 256, GEMM_SMEM>>>(0, bq, bk, bv, bo, out);
    pack_v<<<XN / 8 / 256, 256>>>();
    attn_tc<<<dim3(16, 32), 288, ATTN_SMEM>>>(mask);
    gemm_tc<<<dim3(8, 16, 1), 256, GEMM_SMEM>>>(3, bq, bk, bv, bo, out);
}

// round 15
// speedup vs baseline: 1.3458x; 1.2733x over previous
#include <cuda_runtime.h>
#include <cuda_bf16.h>
#include <cstdint>

#define D_MODEL 2048
#define SEQ     2048
#define BATCH   2
#define NHEADS  16
#define HDIM    128
#define M_TOK   (BATCH*SEQ)   // 4096

#if defined(__CUDA_ARCH_FEAT_SM103_ALL) || defined(__CUDA_ARCH_FEAT_SM100_ALL) || \
    (defined(__CUDA_ARCH_SPECIFIC__) && (__CUDA_ARCH_SPECIFIC__ >= 1000))
#define HAS_TCGEN05 1
#else
#define HAS_TCGEN05 0
#endif

// ---- persistent scratch ----
// GEMM operands: 8KB tiles (128 rows x 32 k, 64B rows, SW64), tile idx (c32*nrt + rt)
__device__ __nv_bfloat16 g_xh[M_TOK * D_MODEL];
__device__ __nv_bfloat16 g_xl[M_TOK * D_MODEL];
__device__ __nv_bfloat16 g_chh[M_TOK * D_MODEL];   // packed ctx (written by attn)
__device__ __nv_bfloat16 g_cll[M_TOK * D_MODEL];
__device__ __nv_bfloat16 g_wh[4][D_MODEL * D_MODEL];
__device__ __nv_bfloat16 g_wl[4][D_MODEL * D_MODEL];

// attention operands (SW128 128B-row formats)
__device__ __nv_bfloat16 g_aqh[M_TOK * D_MODEL];   // Q tiles: [bh][rt16][2ch x 16KB]
__device__ __nv_bfloat16 g_aql[M_TOK * D_MODEL];
__device__ __nv_bfloat16 g_akh[M_TOK * D_MODEL];   // K tiles: [bh][kt32][2ch x 8KB]
__device__ __nv_bfloat16 g_akl[M_TOK * D_MODEL];
__device__ __nv_bfloat16 g_avh[M_TOK * D_MODEL];   // V^T tiles: [bh][kt32][16KB]
__device__ __nv_bfloat16 g_avl[M_TOK * D_MODEL];

// ============================================================
// PTX helpers
// ============================================================
__device__ __forceinline__ uint32_t smem_u32(const void* p) {
    uint32_t a;
    asm("{ .reg .u64 t; cvta.to.shared.u64 t, %1; cvt.u32.u64 %0, t; }" : "=r"(a) : "l"(p));
    return a;
}
__device__ __forceinline__ uint32_t elect_one_pred() {
    uint32_t p;
    asm volatile("{ .reg .pred p; elect.sync _|p, 0xFFFFFFFF; selp.b32 %0, 1, 0, p; }" : "=r"(p));
    return p;
}
static constexpr uint64_t SMEM_DESC_BASE_SW128 =
    (uint64_t(2) << 61) | (uint64_t(1) << 46) | (uint64_t(64) << 32) | (uint64_t(1) << 16);
static constexpr uint64_t SMEM_DESC_BASE_SW64 =
    (uint64_t(4) << 61) | (uint64_t(1) << 46) | (uint64_t(32) << 32) | (uint64_t(1) << 16);
#define MAKE_SMEM_DESC(base_addr) \
    (SMEM_DESC_BASE_SW128 | ((uint64_t)((base_addr) >> 4) & 0x3FFF))
#define MAKE_SMEM_DESC_SW64(base_addr) \
    (SMEM_DESC_BASE_SW64 | ((uint64_t)((base_addr) >> 4) & 0x3FFF))
#define SMEM_SWIZZLE_128B(off) ((off) ^ (((off) >> 3) & 0x70))
#define SMEM_SWIZZLE_64B(off)  ((off) ^ (((off) >> 3) & 0x30))

#define MBARRIER_INIT(mbar, count) \
    asm volatile("mbarrier.init.shared.b64 [%0], %1;" \
                 :: "r"((uint32_t)(mbar)), "r"((uint32_t)(count)) : "memory")
#define MBARRIER_INVAL(mbar) \
    asm volatile("mbarrier.inval.shared.b64 [%0];" :: "r"((uint32_t)(mbar)) : "memory")
#define MBARRIER_EXPECT_TX(mbar, bytes) \
    asm volatile("mbarrier.arrive.expect_tx.shared.b64 _, [%0], %1;" \
                 :: "r"((uint32_t)(mbar)), "r"((uint32_t)(bytes)) : "memory")
#define MBARRIER_ARRIVE(mbar) \
    asm volatile("mbarrier.arrive.shared.b64 _, [%0];" :: "r"((uint32_t)(mbar)) : "memory")
#define MBARRIER_WAIT_PARITY(mbar, parity) do {                                          \
    uint32_t _m = (uint32_t)(mbar);                                                      \
    uint32_t _p = (uint32_t)(parity);                                                    \
    uint32_t _done;                                                                      \
    asm volatile("{ .reg .pred p; mbarrier.try_wait.parity.acquire.cta.shared::cta.b64 " \
                 "p, [%1], %2; selp.b32 %0, 1, 0, p; }"                                  \
                 : "=r"(_done) : "r"(_m), "r"(_p) : "memory");                           \
    if (!_done) {                                                                        \
        asm volatile("{ .reg .pred P1; WL_%=: "                                          \
                     "mbarrier.try_wait.parity.acquire.cta.shared::cta.b64 P1, [%0], %1, 0x989680; " \
                     "@P1 bra.uni WD_%=; bra.uni WL_%=; WD_%=: }"                        \
                     :: "r"(_m), "r"(_p) : "memory");                                    \
    }                                                                                    \
} while (0)

#define BULK_CP(dst_smem, src_gmem, bytes, mbar) \
    asm volatile("cp.async.bulk.shared::cluster.global.mbarrier::complete_tx::bytes " \
                 "[%0], [%1], %2, [%3];" \
                 :: "r"((uint32_t)(dst_smem)), "l"(src_gmem), "r"((uint32_t)(bytes)), \
                    "r"((uint32_t)(mbar)) : "memory")
#define BULK_CP_S2G(dst_gmem, src_smem, bytes) \
    asm volatile("cp.async.bulk.global.shared::cta.bulk_group [%0], [%1], %2;" \
                 :: "l"(dst_gmem), "r"((uint32_t)(src_smem)), "r"((uint32_t)(bytes)) : "memory")
#define BULK_COMMIT() asm volatile("cp.async.bulk.commit_group;" ::: "memory")
#define BULK_WAIT0()  asm volatile("cp.async.bulk.wait_group 0;" ::: "memory")
#define FENCE_PROXY_ASYNC() asm volatile("fence.proxy.async;" ::: "memory")

#if HAS_TCGEN05
#define TCGEN05_ALLOC(smem_addr, nCols) \
    asm volatile("tcgen05.alloc.cta_group::1.sync.aligned.shared::cta.b32 [%0], %1;" \
                 :: "r"((uint32_t)(smem_addr)), "r"((uint32_t)(nCols)) : "memory")
#define TCGEN05_DEALLOC(tmem_addr, nCols) \
    asm volatile("tcgen05.dealloc.cta_group::1.sync.aligned.b32 %0, %1;" \
                 :: "r"(tmem_addr), "r"((uint32_t)(nCols)))
#define TCGEN05_RELINQUISH() \
    asm volatile("tcgen05.relinquish_alloc_permit.cta_group::1.sync.aligned;")
#define TCGEN05_COMMIT(mbar) \
    asm volatile("tcgen05.commit.cta_group::1.mbarrier::arrive::one.shared::cluster.b64 [%0];" \
                 :: "r"((uint32_t)(mbar)) : "memory")
#define TCGEN05_FENCE_AFTER() \
    asm volatile("tcgen05.fence::after_thread_sync;" ::: "memory")
#define TCGEN05_FENCE_BEFORE() \
    asm volatile("tcgen05.fence::before_thread_sync;" ::: "memory")
#define TCGEN05_WAIT_LD() \
    asm volatile("tcgen05.wait::ld.sync.aligned;" ::: "memory")
#define TCGEN05_WAIT_ST() \
    asm volatile("tcgen05.wait::st.sync.aligned;" ::: "memory")

#define TCGEN05_LD_32X32B_X32(r, tmem_addr) \
    asm volatile( \
        "tcgen05.ld.sync.aligned.32x32b.x32.b32 " \
        "{%0, %1, %2, %3, %4, %5, %6, %7, " \
        " %8, %9, %10, %11, %12, %13, %14, %15, " \
        " %16, %17, %18, %19, %20, %21, %22, %23, " \
        " %24, %25, %26, %27, %28, %29, %30, %31}, [%32];" \
        : "=r"((r)[0]),  "=r"((r)[1]),  "=r"((r)[2]),  "=r"((r)[3]), \
          "=r"((r)[4]),  "=r"((r)[5]),  "=r"((r)[6]),  "=r"((r)[7]), \
          "=r"((r)[8]),  "=r"((r)[9]),  "=r"((r)[10]), "=r"((r)[11]), \
          "=r"((r)[12]), "=r"((r)[13]), "=r"((r)[14]), "=r"((r)[15]), \
          "=r"((r)[16]), "=r"((r)[17]), "=r"((r)[18]), "=r"((r)[19]), \
          "=r"((r)[20]), "=r"((r)[21]), "=r"((r)[22]), "=r"((r)[23]), \
          "=r"((r)[24]), "=r"((r)[25]), "=r"((r)[26]), "=r"((r)[27]), \
          "=r"((r)[28]), "=r"((r)[29]), "=r"((r)[30]), "=r"((r)[31]) \
        : "r"(tmem_addr))

#define TCGEN05_ST_32X32B_X32(tmem_addr, r) \
    asm volatile( \
        "tcgen05.st.sync.aligned.32x32b.x32.b32 [%0], " \
        "{%1, %2, %3, %4, %5, %6, %7, %8, " \
        " %9, %10, %11, %12, %13, %14, %15, %16, " \
        " %17, %18, %19, %20, %21, %22, %23, %24, " \
        " %25, %26, %27, %28, %29, %30, %31, %32};" \
        :: "r"(tmem_addr), \
           "r"((r)[0]),  "r"((r)[1]),  "r"((r)[2]),  "r"((r)[3]), \
           "r"((r)[4]),  "r"((r)[5]),  "r"((r)[6]),  "r"((r)[7]), \
           "r"((r)[8]),  "r"((r)[9]),  "r"((r)[10]), "r"((r)[11]), \
           "r"((r)[12]), "r"((r)[13]), "r"((r)[14]), "r"((r)[15]), \
           "r"((r)[16]), "r"((r)[17]), "r"((r)[18]), "r"((r)[19]), \
           "r"((r)[20]), "r"((r)[21]), "r"((r)[22]), "r"((r)[23]), \
           "r"((r)[24]), "r"((r)[25]), "r"((r)[26]), "r"((r)[27]), \
           "r"((r)[28]), "r"((r)[29]), "r"((r)[30]), "r"((r)[31]) \
        : "memory")

#define TCGEN05_ST_32X32B_X16(tmem_addr, r) \
    asm volatile( \
        "tcgen05.st.sync.aligned.32x32b.x16.b32 [%0], " \
        "{%1, %2, %3, %4, %5, %6, %7, %8, " \
        " %9, %10, %11, %12, %13, %14, %15, %16};" \
        :: "r"(tmem_addr), \
           "r"((r)[0]),  "r"((r)[1]),  "r"((r)[2]),  "r"((r)[3]), \
           "r"((r)[4]),  "r"((r)[5]),  "r"((r)[6]),  "r"((r)[7]), \
           "r"((r)[8]),  "r"((r)[9]),  "r"((r)[10]), "r"((r)[11]), \
           "r"((r)[12]), "r"((r)[13]), "r"((r)[14]), "r"((r)[15]) \
        : "memory")

__device__ __forceinline__ void mma_f16_ss(uint32_t d_tmem, uint64_t a_desc, uint64_t b_desc,
                                           uint32_t idesc, uint32_t enable) {
    asm volatile(
        "{\n\t"
        ".reg .pred p;\n\t"
        "setp.ne.u32 p, %4, 0;\n\t"
        "tcgen05.mma.cta_group::1.kind::f16 [%0], %1, %2, %3, {%5, %5, %5, %5}, p;\n\t"
        "}"
        :: "r"(d_tmem), "l"(a_desc), "l"(b_desc), "r"(idesc), "r"(enable), "r"(0u)
        : "memory");
}
__device__ __forceinline__ void mma_f16_ts(uint32_t d_tmem, uint32_t a_tmem, uint64_t b_desc,
                                           uint32_t idesc, uint32_t enable) {
    asm volatile(
        "{\n\t"
        ".reg .pred p;\n\t"
        "setp.ne.u32 p, %4, 0;\n\t"
        "tcgen05.mma.cta_group::1.kind::f16 [%0], [%1], %2, %3, {%5, %5, %5, %5}, p;\n\t"
        "}"
        :: "r"(d_tmem), "r"(a_tmem), "l"(b_desc), "r"(idesc), "r"(enable), "r"(0u)
        : "memory");
}
#endif  // HAS_TCGEN05

__device__ __forceinline__ void split_bf16(float f, __nv_bfloat16& h, __nv_bfloat16& l) {
    h = __float2bfloat16(f);
    l = __float2bfloat16(f - __bfloat162float(h));
}

// ============================================================
// Merged split+pack: x + W0..W3, 8KB-tile SW64 format.
// ============================================================
#define XN8 (M_TOK * D_MODEL / 8)
#define WN8 (D_MODEL * D_MODEL / 8)

__global__ __launch_bounds__(256) void split_all(
    const float* __restrict__ x, const float* __restrict__ W0,
    const float* __restrict__ W1, const float* __restrict__ W2,
    const float* __restrict__ W3)
{
    int i = blockIdx.x * blockDim.x + threadIdx.x;
    const float* src;
    __nv_bfloat16 *hi, *lo;
    int nrt, li;
    if (i < XN8) {
        src = x; hi = g_xh; lo = g_xl; nrt = 32; li = i;
    } else {
        int w = (i - XN8) >> 19;
        li = (i - XN8) & (WN8 - 1);
        src = (w == 0) ? W0 : (w == 1) ? W1 : (w == 2) ? W2 : W3;
        hi = g_wh[w]; lo = g_wl[w]; nrt = 16;
    }
    int elem = li * 8;
    int row = elem >> 11;
    int col = elem & 2047;
    int rt = row >> 7, r = row & 127;
    int c  = col >> 5, kc = col & 31;
    size_t tb = ((size_t)(c * nrt + rt)) << 13;
    uint32_t so = SMEM_SWIZZLE_64B((uint32_t)(r * 64 + kc * 2));

    float4 v0 = ((const float4*)src)[(size_t)li * 2];
    float4 v1 = ((const float4*)src)[(size_t)li * 2 + 1];
    float f[8] = {v0.x, v0.y, v0.z, v0.w, v1.x, v1.y, v1.z, v1.w};
    __align__(16) __nv_bfloat16 h[8], l[8];
#pragma unroll
    for (int j = 0; j < 8; j++) split_bf16(f[j], h[j], l[j]);
    *(uint4*)((char*)hi + tb + so) = *(uint4*)h;
    *(uint4*)((char*)lo + tb + so) = *(uint4*)l;
}

// ============================================================
// tcgen05 GEMM, single CTA computes 256(M) x 256(N).
// mode 0/1 = Q/K proj (packed epilogue), 2 = V (fused V^T pack epilogue),
// 3 = O proj (fp32 out). KCH=32 SW64 tiles, 3 stages x 64KB.
// ============================================================
#define NCH  64
#define TIL8 8192
#define STG  (8 * TIL8)
#define SMB0 1024
#define GEMM_SMEM (SMB0 + 3 * STG)      // 197632
#define GEMM_IDESC 0x8400490u           // F32, BF16xBF16, M=128, N=256
#define NRT_A 32

__global__ __launch_bounds__(256) void gemm_tc(
    int mode_base, const float* __restrict__ b0, const float* __restrict__ b1,
    const float* __restrict__ b2, const float* __restrict__ b3,
    float* __restrict__ out)
{
#if HAS_TCGEN05
    extern __shared__ char sm[];
    const uint32_t smb = smem_u32(sm);
    const int tid = threadIdx.x;
    const int wid = tid >> 5;
    const int lid = tid & 31;
    const int rp = blockIdx.y;           // row-pair: rows [rp*256, rp*256+256)
    const int bx = blockIdx.x;           // 256-col block
    const int mode = mode_base + blockIdx.z;

    const __nv_bfloat16* Ah = (mode < 3) ? g_xh : g_chh;
    const __nv_bfloat16* Al = (mode < 3) ? g_xl : g_cll;
    const __nv_bfloat16* Bh = g_wh[mode];
    const __nv_bfloat16* Bl = g_wl[mode];
    const float* bias = (mode == 0) ? b0 : (mode == 1) ? b1 : (mode == 2) ? b2 : b3;
    const float alpha = (mode == 0) ? 0.08838834764831845f : 1.0f;

    if (wid == 0) TCGEN05_ALLOC(smb + 0, 512);
    if (tid == 0) {
#pragma unroll
        for (int s = 0; s < 3; ++s) {
            MBARRIER_INIT(smb + 64 + 16 * s, 1);    // full (tx)
            MBARRIER_INIT(smb + 112 + 16 * s, 1);   // mma commit
        }
    }
    __syncthreads();

    uint32_t tmem;
    asm volatile("ld.shared.b32 %0, [%1];" : "=r"(tmem) : "r"(smb + 0));

    if (wid == 0 && elect_one_pred()) {
#define LOAD_CHUNK(c, s)                                                        \
        do {                                                                    \
            uint32_t st = smb + SMB0 + (s) * STG;                               \
            uint32_t fb = smb + 64 + 16 * (s);                                  \
            size_t ao = ((size_t)((c) * 32 + 2 * rp)) << 13;                    \
            size_t bo = ((size_t)((c) * 16 + 2 * bx)) << 13;                    \
            MBARRIER_EXPECT_TX(fb, 4 * 2 * TIL8);                               \
            BULK_CP(st,             (const char*)Ah + ao, 2 * TIL8, fb);        \
            BULK_CP(st + 2 * TIL8,  (const char*)Al + ao, 2 * TIL8, fb);        \
            BULK_CP(st + 4 * TIL8,  (const char*)Bh + bo, 2 * TIL8, fb);        \
            BULK_CP(st + 6 * TIL8,  (const char*)Bl + bo, 2 * TIL8, fb);        \
        } while (0)

        LOAD_CHUNK(0, 0);
        LOAD_CHUNK(1, 1);
        LOAD_CHUNK(2, 2);

        for (int c = 0; c < NCH; ++c) {
            int s = c % 3, ph = (c / 3) & 1;
            uint32_t st = smb + SMB0 + s * STG;
            MBARRIER_WAIT_PARITY(smb + 64 + 16 * s, ph);
            uint64_t dBh = MAKE_SMEM_DESC_SW64(st + 4 * TIL8);
            uint64_t dBl = MAKE_SMEM_DESC_SW64(st + 6 * TIL8);
#pragma unroll
            for (int ks = 0; ks < 2; ++ks) {
#pragma unroll
                for (int t = 0; t < 2; ++t) {
                    uint64_t dAh = MAKE_SMEM_DESC_SW64(st + t * TIL8) + ks * 2;
                    uint64_t dAl = MAKE_SMEM_DESC_SW64(st + 2 * TIL8 + t * TIL8) + ks * 2;
                    uint32_t acc = tmem + t * 256;
                    mma_f16_ss(acc, dAh, dBh + ks * 2, GEMM_IDESC, (c | ks) != 0);
                    mma_f16_ss(acc, dAl, dBh + ks * 2, GEMM_IDESC, 1);
                    mma_f16_ss(acc, dAh, dBl + ks * 2, GEMM_IDESC, 1);
                }
            }
            TCGEN05_COMMIT(smb + 112 + 16 * s);
            if (c + 3 < NCH) {
                MBARRIER_WAIT_PARITY(smb + 112 + 16 * s, ph);
                LOAD_CHUNK(c + 3, s);
            }
        }
        MBARRIER_WAIT_PARITY(smb + 112 + 16 * ((NCH - 1) % 3), ((NCH - 1) / 3) & 1);
#undef LOAD_CHUNK
    }
    __syncthreads();
    TCGEN05_FENCE_AFTER();

    const int wg = wid >> 2;
    const int sub = wid & 3;
    const int hd = bx * 2 + wg;

    if (mode == 2) {
        // ---- fused V^T pack epilogue: stage transposed tiles in smem,
        //      bulk-store to g_avh/g_avl. Two 128-token halves. ----
        const int token_local = sub * 32 + lid;     // 0..127 within half
        const int kt2 = token_local >> 6;           // 0/1
        const int sc = token_local & 63;
        char* tbuf = sm + SMB0 + (size_t)(wg * 2 + kt2) * 32768;
#pragma unroll
        for (int t = 0; t < 2; ++t) {
#pragma unroll
            for (int cb = 0; cb < 4; ++cb) {
                uint32_t r[32];
                TCGEN05_LD_32X32B_X32(r, tmem + t * 256 + wg * 128 + cb * 32);
                TCGEN05_WAIT_LD();
                int n0 = bx * 256 + wg * 128 + cb * 32;
#pragma unroll
                for (int j = 0; j < 32; ++j) {
                    float f = __uint_as_float(r[j]) + bias[n0 + j];
                    __nv_bfloat16 hh, ll;
                    split_bf16(f, hh, ll);
                    int d = cb * 32 + j;
                    uint32_t off = SMEM_SWIZZLE_128B((uint32_t)(d * 128 + sc * 2));
                    *(__nv_bfloat16*)(tbuf + off) = hh;
                    *(__nv_bfloat16*)(tbuf + 16384 + off) = ll;
                }
            }
            __syncthreads();
            FENCE_PROXY_ASYNC();
            if (tid < 4) {
                int wg_t = tid >> 1, kt2g = tid & 1;
                int m0 = (rp * 2 + t) * 128;
                int b_ = m0 >> 11;
                int ktg = ((m0 & 2047) >> 6) + kt2g;
                int bh = b_ * 16 + bx * 2 + wg_t;
                size_t dst = ((size_t)(bh * 32 + ktg)) << 14;
                uint32_t sbuf = smb + SMB0 + (uint32_t)tid * 32768;
                BULK_CP_S2G((char*)g_avh + dst, sbuf, 16384);
                BULK_CP_S2G((char*)g_avl + dst, sbuf + 16384, 16384);
                BULK_COMMIT();
                BULK_WAIT0();
            }
            __syncthreads();
        }
        TCGEN05_FENCE_BEFORE();
    } else {
        // ---- generic epilogue (Q/K packed, O fp32) ----
        __align__(16) __nv_bfloat16 hv[8], lv[8];
#pragma unroll
        for (int t = 0; t < 2; ++t) {
            const int m = (rp * 2 + t) * 128 + sub * 32 + lid;
            const int b_ = m >> 11, s_ = m & 2047;
            const int bh2 = b_ * 16 + hd;
#pragma unroll
            for (int cb = 0; cb < 4; ++cb) {
                uint32_t r[32];
                TCGEN05_LD_32X32B_X32(r, tmem + t * 256 + wg * 128 + cb * 32);
                TCGEN05_WAIT_LD();
                int n0 = bx * 256 + wg * 128 + cb * 32;

                if (mode == 3) {
                    float* crow = out + (size_t)m * D_MODEL;
#pragma unroll
                    for (int j = 0; j < 32; j += 4) {
                        float4 o;
                        o.x = __uint_as_float(r[j + 0]) + bias[n0 + j + 0];
                        o.y = __uint_as_float(r[j + 1]) + bias[n0 + j + 1];
                        o.z = __uint_as_float(r[j + 2]) + bias[n0 + j + 2];
                        o.w = __uint_as_float(r[j + 3]) + bias[n0 + j + 3];
                        *(float4*)(crow + n0 + j) = o;
                    }
                } else {
                    size_t tb;
                    uint32_t rr;
                    char *dh, *dl;
                    if (mode == 0) {
                        int rt2 = s_ >> 7; rr = s_ & 127;
                        tb = ((size_t)((bh2 * 16 + rt2) * 2 + (cb >> 1))) << 14;
                        dh = (char*)g_aqh + tb; dl = (char*)g_aql + tb;
                    } else {
                        int kt = s_ >> 6; rr = s_ & 63;
                        tb = ((size_t)((bh2 * 32 + kt) * 2 + (cb >> 1))) << 13;
                        dh = (char*)g_akh + tb; dl = (char*)g_akl + tb;
                    }
                    int kcb = (cb & 1) * 32;
#pragma unroll
                    for (int j0 = 0; j0 < 32; j0 += 8) {
#pragma unroll
                        for (int j = 0; j < 8; ++j) {
                            float f = (__uint_as_float(r[j0 + j]) + bias[n0 + j0 + j]) * alpha;
                            split_bf16(f, hv[j], lv[j]);
                        }
                        uint32_t so = SMEM_SWIZZLE_128B((uint32_t)(rr * 128 + (kcb + j0) * 2));
                        *(uint4*)(dh + so) = *(uint4*)hv;
                        *(uint4*)(dl + so) = *(uint4*)lv;
                    }
                }
            }
        }
        TCGEN05_FENCE_BEFORE();
    }

    __syncthreads();
    if (tid == 0) {
#pragma unroll
        for (int s = 0; s < 3; ++s) {
            MBARRIER_INVAL(smb + 64 + 16 * s);
            MBARRIER_INVAL(smb + 112 + 16 * s);
        }
    }
    __syncthreads();
    if (wid == 0) {
        TCGEN05_RELINQUISH();
        TCGEN05_DEALLOC(tmem, 512);
    }
#endif
}

// ============================================================
// tcgen05 flash attention (8-warp softmax; smax_free barrier removed —
// S-region(i-2) reuse is ordered by the p_ready(i-2) wait before PV(i-2))
// ============================================================
#define AOFF_LBUF 1024
#define AOFF_MASK 2048
#define AOFF_K    10240
#define AOFF_V    75776
#define AOFF_QS   (AOFF_V + 65536)
#define ATTN_SMEM 206848
#define IDESC_S   0x8100490u
#define IDESC_PV  0x8200490u

__global__ __launch_bounds__(288) void attn_tc(const float* __restrict__ mask)
{
#if HAS_TCGEN05
    extern __shared__ char sm[];
    const uint32_t smb = smem_u32(sm);
    const int tid = threadIdx.x;
    const int wid = tid >> 5;
    const int lid = tid & 31;
    const int rt = blockIdx.x;
    const int bh = blockIdx.y;
    const int b = bh >> 4;

    if (wid == 0) TCGEN05_ALLOC(smb + 0, 512);
    if (tid == 0) {
        MBARRIER_INIT(smb + 64, 1);    // qbar (tx)
        MBARRIER_INIT(smb + 80, 4);    // qdone
#pragma unroll
        for (int s = 0; s < 2; ++s) {
            MBARRIER_INIT(smb + 96 + 16 * s, 1);    // full (tx)
            MBARRIER_INIT(smb + 128 + 16 * s, 1);   // s_full (commit)
            MBARRIER_INIT(smb + 192 + 16 * s, 8);   // p_ready
            MBARRIER_INIT(smb + 224 + 16 * s, 1);   // pv_done (commit)
        }
    }
    for (int j = tid; j < SEQ; j += 288) {
        float mv = mask[b * SEQ + j];
        ((float*)(sm + AOFF_MASK))[j] = (1.0f - mv) * -1e30f;
    }
    __syncthreads();

    uint32_t tmem;
    asm volatile("ld.shared.b32 %0, [%1];" : "=r"(tmem) : "r"(smb + 0));

    // ---------------- control warp ----------------
    if (wid == 8) {
        if (elect_one_pred()) {
#define LOADKV(c)                                                          \
            do {                                                           \
                size_t kb = ((size_t)(bh * 32 + (c))) << 14;               \
                uint32_t kst = smb + AOFF_K + ((c) & 1) * 32768;           \
                uint32_t vst = smb + AOFF_V + ((c) & 3) * 32768;           \
                uint32_t fb = smb + 96 + 16 * ((c) & 1);                   \
                MBARRIER_EXPECT_TX(fb, 65536);                             \
                BULK_CP(kst,         (const char*)g_akh + kb, 16384, fb);  \
                BULK_CP(kst + 16384, (const char*)g_akl + kb, 16384, fb);  \
                BULK_CP(vst,         (const char*)g_avh + kb, 16384, fb);  \
                BULK_CP(vst + 16384, (const char*)g_avl + kb, 16384, fb);  \
            } while (0)

            {
                size_t qb = ((size_t)(bh * 16 + rt)) << 15;
                MBARRIER_EXPECT_TX(smb + 64, 65536);
                BULK_CP(smb + AOFF_QS,         (const char*)g_aqh + qb, 32768, smb + 64);
                BULK_CP(smb + AOFF_QS + 32768, (const char*)g_aql + qb, 32768, smb + 64);
                LOADKV(0);
                LOADKV(1);
            }
            MBARRIER_WAIT_PARITY(smb + 80, 0);
            TCGEN05_FENCE_AFTER();

            const uint32_t qh = tmem + 384, ql = tmem + 448;

            for (int i = 0; i < 32; ++i) {
                const int sb = i & 1;
                MBARRIER_WAIT_PARITY(smb + 96 + 16 * sb, (i >> 1) & 1);
                // S-region(i-2) free: guaranteed by p_ready(i-2) wait at iter i-1
                {
                    uint32_t kst = smb + AOFF_K + sb * 32768;
                    uint32_t sreg = tmem + sb * 64;
#pragma unroll
                    for (int st = 0; st < 8; ++st) {
                        uint64_t bh_ = MAKE_SMEM_DESC(kst + (st >> 2) * 8192) + (st & 3) * 2;
                        uint64_t bl_ = MAKE_SMEM_DESC(kst + 16384 + (st >> 2) * 8192) + (st & 3) * 2;
                        mma_f16_ts(sreg, qh + st * 8, bh_, IDESC_S, st != 0);
                        mma_f16_ts(sreg, ql + st * 8, bh_, IDESC_S, 1);
                        mma_f16_ts(sreg, qh + st * 8, bl_, IDESC_S, 1);
                    }
                    TCGEN05_COMMIT(smb + 128 + 16 * sb);
                }
                if (i >= 1) {
                    const int j = i - 1, pb = j & 1, pj = (j >> 1) & 1;
                    MBARRIER_WAIT_PARITY(smb + 192 + 16 * pb, pj);
                    TCGEN05_FENCE_AFTER();
                    uint32_t vst = smb + AOFF_V + (j & 3) * 32768;
                    uint64_t dVh = MAKE_SMEM_DESC(vst);
                    uint64_t dVl = MAKE_SMEM_DESC(vst + 16384);
#pragma unroll
                    for (int ks = 0; ks < 4; ++ks) {
                        uint32_t ah = tmem + 256 + pb * 64 + ks * 8;
                        uint32_t al = tmem + 288 + pb * 64 + ks * 8;
                        mma_f16_ts(tmem + 128, ah, dVh + ks * 2, IDESC_PV, (j | ks) != 0);
                        mma_f16_ts(tmem + 128, al, dVh + ks * 2, IDESC_PV, 1);
                        mma_f16_ts(tmem + 128, ah, dVl + ks * 2, IDESC_PV, 1);
                    }
                    TCGEN05_COMMIT(smb + 224 + 16 * pb);
                }
                if (i <= 29) {
                    MBARRIER_WAIT_PARITY(smb + 128 + 16 * sb, (i >> 1) & 1);
                    if (i >= 2)
                        MBARRIER_WAIT_PARITY(smb + 224 + 16 * (i & 1), ((i - 2) >> 1) & 1);
                    LOADKV(i + 2);
                }
            }
            {
                const int j = 31, pb = 1, pj = 1;
                MBARRIER_WAIT_PARITY(smb + 192 + 16 * pb, pj);
                TCGEN05_FENCE_AFTER();
                uint32_t vst = smb + AOFF_V + (j & 3) * 32768;
                uint64_t dVh = MAKE_SMEM_DESC(vst);
                uint64_t dVl = MAKE_SMEM_DESC(vst + 16384);
#pragma unroll
                for (int ks = 0; ks < 4; ++ks) {
                    uint32_t ah = tmem + 256 + pb * 64 + ks * 8;
                    uint32_t al = tmem + 288 + pb * 64 + ks * 8;
                    mma_f16_ts(tmem + 128, ah, dVh + ks * 2, IDESC_PV, 1);
                    mma_f16_ts(tmem + 128, al, dVh + ks * 2, IDESC_PV, 1);
                    mma_f16_ts(tmem + 128, ah, dVl + ks * 2, IDESC_PV, 1);
                }
                TCGEN05_COMMIT(smb + 224 + 16 * pb);
                MBARRIER_WAIT_PARITY(smb + 224 + 16 * pb, pj);
            }
#undef LOADKV
        }
    }

    // ---------------- softmax warps (8) ----------------
    if (wid < 8) {
        const int sub = wid & 3;
        const int hw  = wid >> 2;
        const uint32_t wo = (uint32_t)sub << 21;
        float l = 0.0f;

        if (wid < 4) {
            MBARRIER_WAIT_PARITY(smb + 64, 0);
            const int r = sub * 32 + lid;
#pragma unroll
            for (int part = 0; part < 4; ++part) {
                uint32_t base = AOFF_QS + (part >> 1) * 32768 + (part & 1) * 16384;
                uint32_t q32[32];
#pragma unroll
                for (int g = 0; g < 8; ++g) {
                    uint32_t off = base + SMEM_SWIZZLE_128B((uint32_t)(r * 128 + g * 16));
                    uint4 v = *(const uint4*)(sm + off);
                    q32[g * 4 + 0] = v.x; q32[g * 4 + 1] = v.y;
                    q32[g * 4 + 2] = v.z; q32[g * 4 + 3] = v.w;
                }
                uint32_t dst = tmem + 384 + (part >> 1) * 64 + (part & 1) * 32 + wo;
                TCGEN05_ST_32X32B_X32(dst, q32);
            }
            TCGEN05_WAIT_ST();
            TCGEN05_FENCE_BEFORE();
            if (elect_one_pred()) MBARRIER_ARRIVE(smb + 80);
        }

        const float* md_base = (const float*)(sm + AOFF_MASK);
        for (int i = 0; i < 32; ++i) {
            int s = i & 1, ph = (i >> 1) & 1;
            MBARRIER_WAIT_PARITY(smb + 128 + 16 * s, ph);
            TCGEN05_FENCE_AFTER();
            uint32_t r0[32];
            TCGEN05_LD_32X32B_X32(r0, tmem + s * 64 + hw * 32);
            TCGEN05_WAIT_LD();

            const float* md = md_base + i * 64 + hw * 32;
#pragma unroll
            for (int j = 0; j < 32; ++j) {
                float e = __expf(__uint_as_float(r0[j]) + md[j]);
                l += e;
                r0[j] = __float_as_uint(e);
            }
            uint32_t phv[16], plv[16];
#pragma unroll
            for (int p = 0; p < 16; ++p) {
                __nv_bfloat16 h0, h1, l0, l1;
                split_bf16(__uint_as_float(r0[2 * p]), h0, l0);
                split_bf16(__uint_as_float(r0[2 * p + 1]), h1, l1);
                __nv_bfloat162 hp(h0, h1), lp(l0, l1);
                phv[p] = *(uint32_t*)&hp;
                plv[p] = *(uint32_t*)&lp;
            }
            TCGEN05_ST_32X32B_X16(tmem + 256 + s * 64 + hw * 16 + wo, phv);
            TCGEN05_ST_32X32B_X16(tmem + 288 + s * 64 + hw * 16 + wo, plv);
            TCGEN05_WAIT_ST();
            TCGEN05_FENCE_BEFORE();
            if (elect_one_pred()) MBARRIER_ARRIVE(smb + 192 + 16 * s);
        }
        ((float*)(sm + AOFF_LBUF))[hw * 128 + sub * 32 + lid] = l;
    }

    __syncthreads();

    // epilogue: normalize O; write ctx in 8KB-tile SW64 GEMM format
    if (wid < 8) {
        TCGEN05_FENCE_AFTER();
        const int sub = wid & 3;
        const int hw = wid >> 2;
        const uint32_t wo = (uint32_t)sub << 21;
        const int row = sub * 32 + lid;
        const float* lbuf = (const float*)(sm + AOFF_LBUF);
        float inv = 1.0f / (lbuf[row] + lbuf[128 + row]);
        int qrow = rt * 128 + row;
        int tok = b * 2048 + qrow;
        int rtt = tok >> 7, rr = tok & 127;
        int hh = bh & 15;
        __align__(16) __nv_bfloat16 hv[8], lv[8];
#pragma unroll
        for (int t = 0; t < 2; ++t) {
            int cb = hw * 2 + t;
            uint32_t r[32];
            TCGEN05_LD_32X32B_X32(r, tmem + 128 + cb * 32 + wo);
            TCGEN05_WAIT_LD();
            int c32 = hh * 4 + cb;
            size_t tb = ((size_t)(c32 * 32 + rtt)) << 13;
#pragma unroll
            for (int j0 = 0; j0 < 32; j0 += 8) {
#pragma unroll
                for (int j = 0; j < 8; ++j)
                    split_bf16(__uint_as_float(r[j0 + j]) * inv, hv[j], lv[j]);
                uint32_t so = SMEM_SWIZZLE_64B((uint32_t)(rr * 64 + j0 * 2));
                *(uint4*)((char*)g_chh + tb + so) = *(uint4*)hv;
                *(uint4*)((char*)g_cll + tb + so) = *(uint4*)lv;
            }
        }
        TCGEN05_FENCE_BEFORE();
    }

    __syncthreads();
    if (tid == 0) {
        MBARRIER_INVAL(smb + 64);
        MBARRIER_INVAL(smb + 80);
#pragma unroll
        for (int s = 0; s < 2; ++s) {
            MBARRIER_INVAL(smb + 96 + 16 * s);
            MBARRIER_INVAL(smb + 128 + 16 * s);
            MBARRIER_INVAL(smb + 192 + 16 * s);
            MBARRIER_INVAL(smb + 224 + 16 * s);
        }
    }
    __syncthreads();
    if (wid == 0) {
        TCGEN05_RELINQUISH();
        TCGEN05_DEALLOC(tmem, 512);
    }
#endif  // HAS_TCGEN05
}

// ============================================================
extern "C" void kernel_launch(void* const* d_in, const int* in_sizes, int n_in,
                              void* d_out, int out_size)
{
    const float* x    = (const float*)d_in[0];
    const float* mask = (const float*)d_in[1];
    const float* Wq   = (const float*)d_in[2];
    const float* bq   = (const float*)d_in[3];
    const float* Wk   = (const float*)d_in[4];
    const float* bk   = (const float*)d_in[5];
    const float* Wv   = (const float*)d_in[6];
    const float* bv   = (const float*)d_in[7];
    const float* Wo   = (const float*)d_in[8];
    const float* bo   = (const float*)d_in[9];
    float* out = (float*)d_out;

    const int TOTAL8 = XN8 + 4 * WN8;

    cudaFuncSetAttribute(gemm_tc, cudaFuncAttributeMaxDynamicSharedMemorySize, GEMM_SMEM);
    cudaFuncSetAttribute(attn_tc, cudaFuncAttributeMaxDynamicSharedMemorySize, ATTN_SMEM);

    split_all<<<TOTAL8 / 256, 256>>>(x, Wq, Wk, Wv, Wo);
    gemm_tc<<<dim3(8, 16, 3), 256, GEMM_SMEM>>>(0, bq, bk, bv, bo, out);
    attn_tc<<<dim3(16, 32), 288, ATTN_SMEM>>>(mask);
    gemm_tc<<<dim3(8, 16, 1), 256, GEMM_SMEM>>>(3, bq, bk, bv, bo, out);
}

// round 16
// speedup vs baseline: 1.5787x; 1.1731x over previous
#include <cuda_runtime.h>
#include <cuda_bf16.h>
#include <cstdint>

#define D_MODEL 2048
#define SEQ     2048
#define BATCH   2
#define NHEADS  16
#define HDIM    128
#define M_TOK   (BATCH*SEQ)   // 4096

#if defined(__CUDA_ARCH_FEAT_SM103_ALL) || defined(__CUDA_ARCH_FEAT_SM100_ALL) || \
    (defined(__CUDA_ARCH_SPECIFIC__) && (__CUDA_ARCH_SPECIFIC__ >= 1000))
#define HAS_TCGEN05 1
#else
#define HAS_TCGEN05 0
#endif

// ---- persistent scratch ----
__device__ __nv_bfloat16 g_xh[M_TOK * D_MODEL];
__device__ __nv_bfloat16 g_xl[M_TOK * D_MODEL];
__device__ __nv_bfloat16 g_chh[M_TOK * D_MODEL];   // packed ctx (written by attn)
__device__ __nv_bfloat16 g_cll[M_TOK * D_MODEL];
__device__ __nv_bfloat16 g_wh[4][D_MODEL * D_MODEL];
__device__ __nv_bfloat16 g_wl[4][D_MODEL * D_MODEL];

__device__ __nv_bfloat16 g_aqh[M_TOK * D_MODEL];   // Q tiles: [bh][rt16][2ch x 16KB]
__device__ __nv_bfloat16 g_aql[M_TOK * D_MODEL];
__device__ __nv_bfloat16 g_akh[M_TOK * D_MODEL];   // K tiles: [bh][kt32][2ch x 8KB]
__device__ __nv_bfloat16 g_akl[M_TOK * D_MODEL];
__device__ __nv_bfloat16 g_avh[M_TOK * D_MODEL];   // V^T tiles: [bh][kt32][16KB]
__device__ __nv_bfloat16 g_avl[M_TOK * D_MODEL];

// ============================================================
// PTX helpers
// ============================================================
__device__ __forceinline__ uint32_t smem_u32(const void* p) {
    uint32_t a;
    asm("{ .reg .u64 t; cvta.to.shared.u64 t, %1; cvt.u32.u64 %0, t; }" : "=r"(a) : "l"(p));
    return a;
}
__device__ __forceinline__ uint32_t elect_one_pred() {
    uint32_t p;
    asm volatile("{ .reg .pred p; elect.sync _|p, 0xFFFFFFFF; selp.b32 %0, 1, 0, p; }" : "=r"(p));
    return p;
}
static constexpr uint64_t SMEM_DESC_BASE_SW128 =
    (uint64_t(2) << 61) | (uint64_t(1) << 46) | (uint64_t(64) << 32) | (uint64_t(1) << 16);
static constexpr uint64_t SMEM_DESC_BASE_SW64 =
    (uint64_t(4) << 61) | (uint64_t(1) << 46) | (uint64_t(32) << 32) | (uint64_t(1) << 16);
#define MAKE_SMEM_DESC(base_addr) \
    (SMEM_DESC_BASE_SW128 | ((uint64_t)((base_addr) >> 4) & 0x3FFF))
#define MAKE_SMEM_DESC_SW64(base_addr) \
    (SMEM_DESC_BASE_SW64 | ((uint64_t)((base_addr) >> 4) & 0x3FFF))
#define SMEM_SWIZZLE_128B(off) ((off) ^ (((off) >> 3) & 0x70))
#define SMEM_SWIZZLE_64B(off)  ((off) ^ (((off) >> 3) & 0x30))

#define MBARRIER_INIT(mbar, count) \
    asm volatile("mbarrier.init.shared.b64 [%0], %1;" \
                 :: "r"((uint32_t)(mbar)), "r"((uint32_t)(count)) : "memory")
#define MBARRIER_INVAL(mbar) \
    asm volatile("mbarrier.inval.shared.b64 [%0];" :: "r"((uint32_t)(mbar)) : "memory")
#define MBARRIER_EXPECT_TX(mbar, bytes) \
    asm volatile("mbarrier.arrive.expect_tx.shared.b64 _, [%0], %1;" \
                 :: "r"((uint32_t)(mbar)), "r"((uint32_t)(bytes)) : "memory")
#define MBARRIER_ARRIVE(mbar) \
    asm volatile("mbarrier.arrive.shared.b64 _, [%0];" :: "r"((uint32_t)(mbar)) : "memory")
#define MBARRIER_WAIT_PARITY(mbar, parity) do {                                          \
    uint32_t _m = (uint32_t)(mbar);                                                      \
    uint32_t _p = (uint32_t)(parity);                                                    \
    uint32_t _done;                                                                      \
    asm volatile("{ .reg .pred p; mbarrier.try_wait.parity.acquire.cta.shared::cta.b64 " \
                 "p, [%1], %2; selp.b32 %0, 1, 0, p; }"                                  \
                 : "=r"(_done) : "r"(_m), "r"(_p) : "memory");                           \
    if (!_done) {                                                                        \
        asm volatile("{ .reg .pred P1; WL_%=: "                                          \
                     "mbarrier.try_wait.parity.acquire.cta.shared::cta.b64 P1, [%0], %1, 0x989680; " \
                     "@P1 bra.uni WD_%=; bra.uni WL_%=; WD_%=: }"                        \
                     :: "r"(_m), "r"(_p) : "memory");                                    \
    }                                                                                    \
} while (0)

#define BULK_CP(dst_smem, src_gmem, bytes, mbar) \
    asm volatile("cp.async.bulk.shared::cluster.global.mbarrier::complete_tx::bytes " \
                 "[%0], [%1], %2, [%3];" \
                 :: "r"((uint32_t)(dst_smem)), "l"(src_gmem), "r"((uint32_t)(bytes)), \
                    "r"((uint32_t)(mbar)) : "memory")
#define BULK_CP_S2G(dst_gmem, src_smem, bytes) \
    asm volatile("cp.async.bulk.global.shared::cta.bulk_group [%0], [%1], %2;" \
                 :: "l"(dst_gmem), "r"((uint32_t)(src_smem)), "r"((uint32_t)(bytes)) : "memory")
#define BULK_COMMIT() asm volatile("cp.async.bulk.commit_group;" ::: "memory")
#define BULK_WAIT0()  asm volatile("cp.async.bulk.wait_group 0;" ::: "memory")
#define FENCE_PROXY_ASYNC() asm volatile("fence.proxy.async;" ::: "memory")

#if HAS_TCGEN05
#define TCGEN05_ALLOC(smem_addr, nCols) \
    asm volatile("tcgen05.alloc.cta_group::1.sync.aligned.shared::cta.b32 [%0], %1;" \
                 :: "r"((uint32_t)(smem_addr)), "r"((uint32_t)(nCols)) : "memory")
#define TCGEN05_DEALLOC(tmem_addr, nCols) \
    asm volatile("tcgen05.dealloc.cta_group::1.sync.aligned.b32 %0, %1;" \
                 :: "r"(tmem_addr), "r"((uint32_t)(nCols)))
#define TCGEN05_RELINQUISH() \
    asm volatile("tcgen05.relinquish_alloc_permit.cta_group::1.sync.aligned;")
#define TCGEN05_COMMIT(mbar) \
    asm volatile("tcgen05.commit.cta_group::1.mbarrier::arrive::one.shared::cluster.b64 [%0];" \
                 :: "r"((uint32_t)(mbar)) : "memory")
#define TCGEN05_FENCE_AFTER() \
    asm volatile("tcgen05.fence::after_thread_sync;" ::: "memory")
#define TCGEN05_FENCE_BEFORE() \
    asm volatile("tcgen05.fence::before_thread_sync;" ::: "memory")
#define TCGEN05_WAIT_LD() \
    asm volatile("tcgen05.wait::ld.sync.aligned;" ::: "memory")
#define TCGEN05_WAIT_ST() \
    asm volatile("tcgen05.wait::st.sync.aligned;" ::: "memory")

#define TCGEN05_LD_32X32B_X32(r, tmem_addr) \
    asm volatile( \
        "tcgen05.ld.sync.aligned.32x32b.x32.b32 " \
        "{%0, %1, %2, %3, %4, %5, %6, %7, " \
        " %8, %9, %10, %11, %12, %13, %14, %15, " \
        " %16, %17, %18, %19, %20, %21, %22, %23, " \
        " %24, %25, %26, %27, %28, %29, %30, %31}, [%32];" \
        : "=r"((r)[0]),  "=r"((r)[1]),  "=r"((r)[2]),  "=r"((r)[3]), \
          "=r"((r)[4]),  "=r"((r)[5]),  "=r"((r)[6]),  "=r"((r)[7]), \
          "=r"((r)[8]),  "=r"((r)[9]),  "=r"((r)[10]), "=r"((r)[11]), \
          "=r"((r)[12]), "=r"((r)[13]), "=r"((r)[14]), "=r"((r)[15]), \
          "=r"((r)[16]), "=r"((r)[17]), "=r"((r)[18]), "=r"((r)[19]), \
          "=r"((r)[20]), "=r"((r)[21]), "=r"((r)[22]), "=r"((r)[23]), \
          "=r"((r)[24]), "=r"((r)[25]), "=r"((r)[26]), "=r"((r)[27]), \
          "=r"((r)[28]), "=r"((r)[29]), "=r"((r)[30]), "=r"((r)[31]) \
        : "r"(tmem_addr))

#define TCGEN05_ST_32X32B_X32(tmem_addr, r) \
    asm volatile( \
        "tcgen05.st.sync.aligned.32x32b.x32.b32 [%0], " \
        "{%1, %2, %3, %4, %5, %6, %7, %8, " \
        " %9, %10, %11, %12, %13, %14, %15, %16, " \
        " %17, %18, %19, %20, %21, %22, %23, %24, " \
        " %25, %26, %27, %28, %29, %30, %31, %32};" \
        :: "r"(tmem_addr), \
           "r"((r)[0]),  "r"((r)[1]),  "r"((r)[2]),  "r"((r)[3]), \
           "r"((r)[4]),  "r"((r)[5]),  "r"((r)[6]),  "r"((r)[7]), \
           "r"((r)[8]),  "r"((r)[9]),  "r"((r)[10]), "r"((r)[11]), \
           "r"((r)[12]), "r"((r)[13]), "r"((r)[14]), "r"((r)[15]), \
           "r"((r)[16]), "r"((r)[17]), "r"((r)[18]), "r"((r)[19]), \
           "r"((r)[20]), "r"((r)[21]), "r"((r)[22]), "r"((r)[23]), \
           "r"((r)[24]), "r"((r)[25]), "r"((r)[26]), "r"((r)[27]), \
           "r"((r)[28]), "r"((r)[29]), "r"((r)[30]), "r"((r)[31]) \
        : "memory")

#define TCGEN05_ST_32X32B_X16(tmem_addr, r) \
    asm volatile( \
        "tcgen05.st.sync.aligned.32x32b.x16.b32 [%0], " \
        "{%1, %2, %3, %4, %5, %6, %7, %8, " \
        " %9, %10, %11, %12, %13, %14, %15, %16};" \
        :: "r"(tmem_addr), \
           "r"((r)[0]),  "r"((r)[1]),  "r"((r)[2]),  "r"((r)[3]), \
           "r"((r)[4]),  "r"((r)[5]),  "r"((r)[6]),  "r"((r)[7]), \
           "r"((r)[8]),  "r"((r)[9]),  "r"((r)[10]), "r"((r)[11]), \
           "r"((r)[12]), "r"((r)[13]), "r"((r)[14]), "r"((r)[15]) \
        : "memory")

__device__ __forceinline__ void mma_f16_ss(uint32_t d_tmem, uint64_t a_desc, uint64_t b_desc,
                                           uint32_t idesc, uint32_t enable) {
    asm volatile(
        "{\n\t"
        ".reg .pred p;\n\t"
        "setp.ne.u32 p, %4, 0;\n\t"
        "tcgen05.mma.cta_group::1.kind::f16 [%0], %1, %2, %3, {%5, %5, %5, %5}, p;\n\t"
        "}"
        :: "r"(d_tmem), "l"(a_desc), "l"(b_desc), "r"(idesc), "r"(enable), "r"(0u)
        : "memory");
}
__device__ __forceinline__ void mma_f16_ts(uint32_t d_tmem, uint32_t a_tmem, uint64_t b_desc,
                                           uint32_t idesc, uint32_t enable) {
    asm volatile(
        "{\n\t"
        ".reg .pred p;\n\t"
        "setp.ne.u32 p, %4, 0;\n\t"
        "tcgen05.mma.cta_group::1.kind::f16 [%0], [%1], %2, %3, {%5, %5, %5, %5}, p;\n\t"
        "}"
        :: "r"(d_tmem), "r"(a_tmem), "l"(b_desc), "r"(idesc), "r"(enable), "r"(0u)
        : "memory");
}
#endif  // HAS_TCGEN05

__device__ __forceinline__ void split_bf16(float f, __nv_bfloat16& h, __nv_bfloat16& l) {
    h = __float2bfloat16(f);
    l = __float2bfloat16(f - __bfloat162float(h));
}

// ============================================================
// Merged split+pack: x + W0..W3, 8KB-tile SW64 format.
// ============================================================
#define XN8 (M_TOK * D_MODEL / 8)
#define WN8 (D_MODEL * D_MODEL / 8)

__global__ __launch_bounds__(256) void split_all(
    const float* __restrict__ x, const float* __restrict__ W0,
    const float* __restrict__ W1, const float* __restrict__ W2,
    const float* __restrict__ W3)
{
    int i = blockIdx.x * blockDim.x + threadIdx.x;
    const float* src;
    __nv_bfloat16 *hi, *lo;
    int nrt, li;
    if (i < XN8) {
        src = x; hi = g_xh; lo = g_xl; nrt = 32; li = i;
    } else {
        int w = (i - XN8) >> 19;
        li = (i - XN8) & (WN8 - 1);
        src = (w == 0) ? W0 : (w == 1) ? W1 : (w == 2) ? W2 : W3;
        hi = g_wh[w]; lo = g_wl[w]; nrt = 16;
    }
    int elem = li * 8;
    int row = elem >> 11;
    int col = elem & 2047;
    int rt = row >> 7, r = row & 127;
    int c  = col >> 5, kc = col & 31;
    size_t tb = ((size_t)(c * nrt + rt)) << 13;
    uint32_t so = SMEM_SWIZZLE_64B((uint32_t)(r * 64 + kc * 2));

    float4 v0 = ((const float4*)src)[(size_t)li * 2];
    float4 v1 = ((const float4*)src)[(size_t)li * 2 + 1];
    float f[8] = {v0.x, v0.y, v0.z, v0.w, v1.x, v1.y, v1.z, v1.w};
    __align__(16) __nv_bfloat16 h[8], l[8];
#pragma unroll
    for (int j = 0; j < 8; j++) split_bf16(f[j], h[j], l[j]);
    *(uint4*)((char*)hi + tb + so) = *(uint4*)h;
    *(uint4*)((char*)lo + tb + so) = *(uint4*)l;
}

// ============================================================
// tcgen05 GEMM, 256x256/CTA, warp-specialized:
//   warp 0 = MMA issuer (waits only 'full'), warp 1 = loader
//   (waits commit(c-3) for stage reuse -> MMA issue never blocked
//    on MMA completion).
// ============================================================
#define NCH  64
#define TIL8 8192
#define STG  (8 * TIL8)
#define SMB0 1024
#define GEMM_SMEM (SMB0 + 3 * STG)      // 197632
#define GEMM_IDESC 0x8400490u
#define NRT_A 32

__global__ __launch_bounds__(256) void gemm_tc(
    int mode_base, const float* __restrict__ b0, const float* __restrict__ b1,
    const float* __restrict__ b2, const float* __restrict__ b3,
    float* __restrict__ out)
{
#if HAS_TCGEN05
    extern __shared__ char sm[];
    const uint32_t smb = smem_u32(sm);
    const int tid = threadIdx.x;
    const int wid = tid >> 5;
    const int lid = tid & 31;
    const int rp = blockIdx.y;
    const int bx = blockIdx.x;
    const int mode = mode_base + blockIdx.z;

    const __nv_bfloat16* Ah = (mode < 3) ? g_xh : g_chh;
    const __nv_bfloat16* Al = (mode < 3) ? g_xl : g_cll;
    const __nv_bfloat16* Bh = g_wh[mode];
    const __nv_bfloat16* Bl = g_wl[mode];
    const float* bias = (mode == 0) ? b0 : (mode == 1) ? b1 : (mode == 2) ? b2 : b3;
    const float alpha = (mode == 0) ? 0.08838834764831845f : 1.0f;

    if (wid == 0) TCGEN05_ALLOC(smb + 0, 512);
    if (tid == 0) {
#pragma unroll
        for (int s = 0; s < 3; ++s) {
            MBARRIER_INIT(smb + 64 + 16 * s, 1);    // full (tx)
            MBARRIER_INIT(smb + 112 + 16 * s, 1);   // mma commit
        }
    }
    __syncthreads();

    uint32_t tmem;
    asm volatile("ld.shared.b32 %0, [%1];" : "=r"(tmem) : "r"(smb + 0));

#define LOAD_CHUNK(c, s)                                                        \
    do {                                                                        \
        uint32_t st = smb + SMB0 + (s) * STG;                                   \
        uint32_t fb = smb + 64 + 16 * (s);                                      \
        size_t ao = ((size_t)((c) * 32 + 2 * rp)) << 13;                        \
        size_t bo = ((size_t)((c) * 16 + 2 * bx)) << 13;                        \
        MBARRIER_EXPECT_TX(fb, 4 * 2 * TIL8);                                   \
        BULK_CP(st,             (const char*)Ah + ao, 2 * TIL8, fb);            \
        BULK_CP(st + 2 * TIL8,  (const char*)Al + ao, 2 * TIL8, fb);            \
        BULK_CP(st + 4 * TIL8,  (const char*)Bh + bo, 2 * TIL8, fb);            \
        BULK_CP(st + 6 * TIL8,  (const char*)Bl + bo, 2 * TIL8, fb);            \
    } while (0)

    if (wid == 1 && elect_one_pred()) {
        // loader warp: paces on MMA commits 3 stages behind
        LOAD_CHUNK(0, 0);
        LOAD_CHUNK(1, 1);
        LOAD_CHUNK(2, 2);
        for (int c = 3; c < NCH; ++c) {
            int pc = c - 3;
            MBARRIER_WAIT_PARITY(smb + 112 + 16 * (pc % 3), (pc / 3) & 1);
            LOAD_CHUNK(c, c % 3);
        }
    }
    if (wid == 0 && elect_one_pred()) {
        // MMA warp: only waits for data
        for (int c = 0; c < NCH; ++c) {
            int s = c % 3, ph = (c / 3) & 1;
            uint32_t st = smb + SMB0 + s * STG;
            MBARRIER_WAIT_PARITY(smb + 64 + 16 * s, ph);
            uint64_t dBh = MAKE_SMEM_DESC_SW64(st + 4 * TIL8);
            uint64_t dBl = MAKE_SMEM_DESC_SW64(st + 6 * TIL8);
#pragma unroll
            for (int ks = 0; ks < 2; ++ks) {
#pragma unroll
                for (int t = 0; t < 2; ++t) {
                    uint64_t dAh = MAKE_SMEM_DESC_SW64(st + t * TIL8) + ks * 2;
                    uint64_t dAl = MAKE_SMEM_DESC_SW64(st + 2 * TIL8 + t * TIL8) + ks * 2;
                    uint32_t acc = tmem + t * 256;
                    mma_f16_ss(acc, dAh, dBh + ks * 2, GEMM_IDESC, (c | ks) != 0);
                    mma_f16_ss(acc, dAl, dBh + ks * 2, GEMM_IDESC, 1);
                    mma_f16_ss(acc, dAh, dBl + ks * 2, GEMM_IDESC, 1);
                }
            }
            TCGEN05_COMMIT(smb + 112 + 16 * s);
        }
        MBARRIER_WAIT_PARITY(smb + 112 + 16 * ((NCH - 1) % 3), ((NCH - 1) / 3) & 1);
    }
#undef LOAD_CHUNK
    __syncthreads();
    TCGEN05_FENCE_AFTER();

    const int wg = wid >> 2;
    const int sub = wid & 3;
    const int hd = bx * 2 + wg;

    if (mode == 2) {
        // fused V^T pack epilogue (validated R15)
        const int token_local = sub * 32 + lid;
        const int kt2 = token_local >> 6;
        const int sc = token_local & 63;
        char* tbuf = sm + SMB0 + (size_t)(wg * 2 + kt2) * 32768;
#pragma unroll
        for (int t = 0; t < 2; ++t) {
#pragma unroll
            for (int cb = 0; cb < 4; ++cb) {
                uint32_t r[32];
                TCGEN05_LD_32X32B_X32(r, tmem + t * 256 + wg * 128 + cb * 32);
                TCGEN05_WAIT_LD();
                int n0 = bx * 256 + wg * 128 + cb * 32;
#pragma unroll
                for (int j = 0; j < 32; ++j) {
                    float f = __uint_as_float(r[j]) + bias[n0 + j];
                    __nv_bfloat16 hh, ll;
                    split_bf16(f, hh, ll);
                    int d = cb * 32 + j;
                    uint32_t off = SMEM_SWIZZLE_128B((uint32_t)(d * 128 + sc * 2));
                    *(__nv_bfloat16*)(tbuf + off) = hh;
                    *(__nv_bfloat16*)(tbuf + 16384 + off) = ll;
                }
            }
            __syncthreads();
            FENCE_PROXY_ASYNC();
            if (tid < 4) {
                int wg_t = tid >> 1, kt2g = tid & 1;
                int m0 = (rp * 2 + t) * 128;
                int b_ = m0 >> 11;
                int ktg = ((m0 & 2047) >> 6) + kt2g;
                int bh = b_ * 16 + bx * 2 + wg_t;
                size_t dst = ((size_t)(bh * 32 + ktg)) << 14;
                uint32_t sbuf = smb + SMB0 + (uint32_t)tid * 32768;
                BULK_CP_S2G((char*)g_avh + dst, sbuf, 16384);
                BULK_CP_S2G((char*)g_avl + dst, sbuf + 16384, 16384);
                BULK_COMMIT();
                BULK_WAIT0();
            }
            __syncthreads();
        }
        TCGEN05_FENCE_BEFORE();
    } else {
        __align__(16) __nv_bfloat16 hv[8], lv[8];
#pragma unroll
        for (int t = 0; t < 2; ++t) {
            const int m = (rp * 2 + t) * 128 + sub * 32 + lid;
            const int b_ = m >> 11, s_ = m & 2047;
            const int bh2 = b_ * 16 + hd;
#pragma unroll
            for (int cb = 0; cb < 4; ++cb) {
                uint32_t r[32];
                TCGEN05_LD_32X32B_X32(r, tmem + t * 256 + wg * 128 + cb * 32);
                TCGEN05_WAIT_LD();
                int n0 = bx * 256 + wg * 128 + cb * 32;

                if (mode == 3) {
                    float* crow = out + (size_t)m * D_MODEL;
#pragma unroll
                    for (int j = 0; j < 32; j += 4) {
                        float4 o;
                        o.x = __uint_as_float(r[j + 0]) + bias[n0 + j + 0];
                        o.y = __uint_as_float(r[j + 1]) + bias[n0 + j + 1];
                        o.z = __uint_as_float(r[j + 2]) + bias[n0 + j + 2];
                        o.w = __uint_as_float(r[j + 3]) + bias[n0 + j + 3];
                        *(float4*)(crow + n0 + j) = o;
                    }
                } else {
                    size_t tb;
                    uint32_t rr;
                    char *dh, *dl;
                    if (mode == 0) {
                        int rt2 = s_ >> 7; rr = s_ & 127;
                        tb = ((size_t)((bh2 * 16 + rt2) * 2 + (cb >> 1))) << 14;
                        dh = (char*)g_aqh + tb; dl = (char*)g_aql + tb;
                    } else {
                        int kt = s_ >> 6; rr = s_ & 63;
                        tb = ((size_t)((bh2 * 32 + kt) * 2 + (cb >> 1))) << 13;
                        dh = (char*)g_akh + tb; dl = (char*)g_akl + tb;
                    }
                    int kcb = (cb & 1) * 32;
#pragma unroll
                    for (int j0 = 0; j0 < 32; j0 += 8) {
#pragma unroll
                        for (int j = 0; j < 8; ++j) {
                            float f = (__uint_as_float(r[j0 + j]) + bias[n0 + j0 + j]) * alpha;
                            split_bf16(f, hv[j], lv[j]);
                        }
                        uint32_t so = SMEM_SWIZZLE_128B((uint32_t)(rr * 128 + (kcb + j0) * 2));
                        *(uint4*)(dh + so) = *(uint4*)hv;
                        *(uint4*)(dl + so) = *(uint4*)lv;
                    }
                }
            }
        }
        TCGEN05_FENCE_BEFORE();
    }

    __syncthreads();
    if (tid == 0) {
#pragma unroll
        for (int s = 0; s < 3; ++s) {
            MBARRIER_INVAL(smb + 64 + 16 * s);
            MBARRIER_INVAL(smb + 112 + 16 * s);
        }
    }
    __syncthreads();
    if (wid == 0) {
        TCGEN05_RELINQUISH();
        TCGEN05_DEALLOC(tmem, 512);
    }
#endif
}

// ============================================================
// tcgen05 flash attention: warps 0-7 softmax, warp 8 MMA issuer,
// warp 9 loader (all load waits moved off the MMA-issue path).
// ============================================================
#define AOFF_LBUF 1024
#define AOFF_MASK 2048
#define AOFF_K    10240
#define AOFF_V    75776
#define AOFF_QS   (AOFF_V + 65536)
#define ATTN_SMEM 206848
#define IDESC_S   0x8100490u
#define IDESC_PV  0x8200490u

__global__ __launch_bounds__(320) void attn_tc(const float* __restrict__ mask)
{
#if HAS_TCGEN05
    extern __shared__ char sm[];
    const uint32_t smb = smem_u32(sm);
    const int tid = threadIdx.x;
    const int wid = tid >> 5;
    const int lid = tid & 31;
    const int rt = blockIdx.x;
    const int bh = blockIdx.y;
    const int b = bh >> 4;

    if (wid == 0) TCGEN05_ALLOC(smb + 0, 512);
    if (tid == 0) {
        MBARRIER_INIT(smb + 64, 1);    // qbar (tx)
        MBARRIER_INIT(smb + 80, 4);    // qdone
#pragma unroll
        for (int s = 0; s < 2; ++s) {
            MBARRIER_INIT(smb + 96 + 16 * s, 1);    // full (tx)
            MBARRIER_INIT(smb + 128 + 16 * s, 1);   // s_full (commit)
            MBARRIER_INIT(smb + 192 + 16 * s, 8);   // p_ready
            MBARRIER_INIT(smb + 224 + 16 * s, 1);   // pv_done (commit)
        }
    }
    for (int j = tid; j < SEQ; j += 320) {
        float mv = mask[b * SEQ + j];
        ((float*)(sm + AOFF_MASK))[j] = (1.0f - mv) * -1e30f;
    }
    __syncthreads();

    uint32_t tmem;
    asm volatile("ld.shared.b32 %0, [%1];" : "=r"(tmem) : "r"(smb + 0));

#define LOADKV(c)                                                          \
    do {                                                                   \
        size_t kb = ((size_t)(bh * 32 + (c))) << 14;                       \
        uint32_t kst = smb + AOFF_K + ((c) & 1) * 32768;                   \
        uint32_t vst = smb + AOFF_V + ((c) & 3) * 32768;                   \
        uint32_t fb = smb + 96 + 16 * ((c) & 1);                           \
        MBARRIER_EXPECT_TX(fb, 65536);                                     \
        BULK_CP(kst,         (const char*)g_akh + kb, 16384, fb);          \
        BULK_CP(kst + 16384, (const char*)g_akl + kb, 16384, fb);          \
        BULK_CP(vst,         (const char*)g_avh + kb, 16384, fb);          \
        BULK_CP(vst + 16384, (const char*)g_avl + kb, 16384, fb);          \
    } while (0)

    // ---------------- loader warp ----------------
    if (wid == 9) {
        if (elect_one_pred()) {
            {
                size_t qb = ((size_t)(bh * 16 + rt)) << 15;
                MBARRIER_EXPECT_TX(smb + 64, 65536);
                BULK_CP(smb + AOFF_QS,         (const char*)g_aqh + qb, 32768, smb + 64);
                BULK_CP(smb + AOFF_QS + 32768, (const char*)g_aql + qb, 32768, smb + 64);
                LOADKV(0);
                LOADKV(1);
            }
            for (int c = 2; c < 32; ++c) {
                // K stage (c&1) overwrites K(c-2): wait S(c-2) MMAs done
                MBARRIER_WAIT_PARITY(smb + 128 + 16 * ((c - 2) & 1), ((c - 2) >> 1) & 1);
                // V stage (c&3) overwrites V(c-4): wait PV(c-4) done
                if (c >= 4)
                    MBARRIER_WAIT_PARITY(smb + 224 + 16 * ((c - 4) & 1), ((c - 4) >> 1) & 1);
                LOADKV(c);
            }
        }
    }

    // ---------------- MMA warp ----------------
    if (wid == 8) {
        if (elect_one_pred()) {
            MBARRIER_WAIT_PARITY(smb + 80, 0);   // Q in TMEM
            TCGEN05_FENCE_AFTER();

            const uint32_t qh = tmem + 384, ql = tmem + 448;

            for (int i = 0; i < 32; ++i) {
                const int sb = i & 1;
                MBARRIER_WAIT_PARITY(smb + 96 + 16 * sb, (i >> 1) & 1);   // data
                // S-region(i-2) free: ordered by p_ready(i-2) wait at iter i-1
                {
                    uint32_t kst = smb + AOFF_K + sb * 32768;
                    uint32_t sreg = tmem + sb * 64;
#pragma unroll
                    for (int st = 0; st < 8; ++st) {
                        uint64_t bh_ = MAKE_SMEM_DESC(kst + (st >> 2) * 8192) + (st & 3) * 2;
                        uint64_t bl_ = MAKE_SMEM_DESC(kst + 16384 + (st >> 2) * 8192) + (st & 3) * 2;
                        mma_f16_ts(sreg, qh + st * 8, bh_, IDESC_S, st != 0);
                        mma_f16_ts(sreg, ql + st * 8, bh_, IDESC_S, 1);
                        mma_f16_ts(sreg, qh + st * 8, bl_, IDESC_S, 1);
                    }
                    TCGEN05_COMMIT(smb + 128 + 16 * sb);
                }
                if (i >= 1) {
                    const int j = i - 1, pb = j & 1, pj = (j >> 1) & 1;
                    MBARRIER_WAIT_PARITY(smb + 192 + 16 * pb, pj);
                    TCGEN05_FENCE_AFTER();
                    uint32_t vst = smb + AOFF_V + (j & 3) * 32768;
                    uint64_t dVh = MAKE_SMEM_DESC(vst);
                    uint64_t dVl = MAKE_SMEM_DESC(vst + 16384);
#pragma unroll
                    for (int ks = 0; ks < 4; ++ks) {
                        uint32_t ah = tmem + 256 + pb * 64 + ks * 8;
                        uint32_t al = tmem + 288 + pb * 64 + ks * 8;
                        mma_f16_ts(tmem + 128, ah, dVh + ks * 2, IDESC_PV, (j | ks) != 0);
                        mma_f16_ts(tmem + 128, al, dVh + ks * 2, IDESC_PV, 1);
                        mma_f16_ts(tmem + 128, ah, dVl + ks * 2, IDESC_PV, 1);
                    }
                    TCGEN05_COMMIT(smb + 224 + 16 * pb);
                }
            }
            {   // final PV: j = 31
                const int j = 31, pb = 1, pj = 1;
                MBARRIER_WAIT_PARITY(smb + 192 + 16 * pb, pj);
                TCGEN05_FENCE_AFTER();
                uint32_t vst = smb + AOFF_V + (j & 3) * 32768;
                uint64_t dVh = MAKE_SMEM_DESC(vst);
                uint64_t dVl = MAKE_SMEM_DESC(vst + 16384);
#pragma unroll
                for (int ks = 0; ks < 4; ++ks) {
                    uint32_t ah = tmem + 256 + pb * 64 + ks * 8;
                    uint32_t al = tmem + 288 + pb * 64 + ks * 8;
                    mma_f16_ts(tmem + 128, ah, dVh + ks * 2, IDESC_PV, 1);
                    mma_f16_ts(tmem + 128, al, dVh + ks * 2, IDESC_PV, 1);
                    mma_f16_ts(tmem + 128, ah, dVl + ks * 2, IDESC_PV, 1);
                }
                TCGEN05_COMMIT(smb + 224 + 16 * pb);
                MBARRIER_WAIT_PARITY(smb + 224 + 16 * pb, pj);
            }
        }
    }
#undef LOADKV

    // ---------------- softmax warps (8) ----------------
    if (wid < 8) {
        const int sub = wid & 3;
        const int hw  = wid >> 2;
        const uint32_t wo = (uint32_t)sub << 21;
        float l = 0.0f;

        if (wid < 4) {
            MBARRIER_WAIT_PARITY(smb + 64, 0);
            const int r = sub * 32 + lid;
#pragma unroll
            for (int part = 0; part < 4; ++part) {
                uint32_t base = AOFF_QS + (part >> 1) * 32768 + (part & 1) * 16384;
                uint32_t q32[32];
#pragma unroll
                for (int g = 0; g < 8; ++g) {
                    uint32_t off = base + SMEM_SWIZZLE_128B((uint32_t)(r * 128 + g * 16));
                    uint4 v = *(const uint4*)(sm + off);
                    q32[g * 4 + 0] = v.x; q32[g * 4 + 1] = v.y;
                    q32[g * 4 + 2] = v.z; q32[g * 4 + 3] = v.w;
                }
                uint32_t dst = tmem + 384 + (part >> 1) * 64 + (part & 1) * 32 + wo;
                TCGEN05_ST_32X32B_X32(dst, q32);
            }
            TCGEN05_WAIT_ST();
            TCGEN05_FENCE_BEFORE();
            if (elect_one_pred()) MBARRIER_ARRIVE(smb + 80);
        }

        const float* md_base = (const float*)(sm + AOFF_MASK);
        for (int i = 0; i < 32; ++i) {
            int s = i & 1, ph = (i >> 1) & 1;
            MBARRIER_WAIT_PARITY(smb + 128 + 16 * s, ph);
            TCGEN05_FENCE_AFTER();
            uint32_t r0[32];
            TCGEN05_LD_32X32B_X32(r0, tmem + s * 64 + hw * 32);
            TCGEN05_WAIT_LD();

            const float* md = md_base + i * 64 + hw * 32;
#pragma unroll
            for (int j = 0; j < 32; ++j) {
                float e = __expf(__uint_as_float(r0[j]) + md[j]);
                l += e;
                r0[j] = __float_as_uint(e);
            }
            uint32_t phv[16], plv[16];
#pragma unroll
            for (int p = 0; p < 16; ++p) {
                __nv_bfloat16 h0, h1, l0, l1;
                split_bf16(__uint_as_float(r0[2 * p]), h0, l0);
                split_bf16(__uint_as_float(r0[2 * p + 1]), h1, l1);
                __nv_bfloat162 hp(h0, h1), lp(l0, l1);
                phv[p] = *(uint32_t*)&hp;
                plv[p] = *(uint32_t*)&lp;
            }
            TCGEN05_ST_32X32B_X16(tmem + 256 + s * 64 + hw * 16 + wo, phv);
            TCGEN05_ST_32X32B_X16(tmem + 288 + s * 64 + hw * 16 + wo, plv);
            TCGEN05_WAIT_ST();
            TCGEN05_FENCE_BEFORE();
            if (elect_one_pred()) MBARRIER_ARRIVE(smb + 192 + 16 * s);
        }
        ((float*)(sm + AOFF_LBUF))[hw * 128 + sub * 32 + lid] = l;
    }

    __syncthreads();

    // epilogue: normalize O; write ctx in 8KB-tile SW64 GEMM format
    if (wid < 8) {
        TCGEN05_FENCE_AFTER();
        const int sub = wid & 3;
        const int hw = wid >> 2;
        const uint32_t wo = (uint32_t)sub << 21;
        const int row = sub * 32 + lid;
        const float* lbuf = (const float*)(sm + AOFF_LBUF);
        float inv = 1.0f / (lbuf[row] + lbuf[128 + row]);
        int qrow = rt * 128 + row;
        int tok = b * 2048 + qrow;
        int rtt = tok >> 7, rr = tok & 127;
        int hh = bh & 15;
        __align__(16) __nv_bfloat16 hv[8], lv[8];
#pragma unroll
        for (int t = 0; t < 2; ++t) {
            int cb = hw * 2 + t;
            uint32_t r[32];
            TCGEN05_LD_32X32B_X32(r, tmem + 128 + cb * 32 + wo);
            TCGEN05_WAIT_LD();
            int c32 = hh * 4 + cb;
            size_t tb = ((size_t)(c32 * 32 + rtt)) << 13;
#pragma unroll
            for (int j0 = 0; j0 < 32; j0 += 8) {
#pragma unroll
                for (int j = 0; j < 8; ++j)
                    split_bf16(__uint_as_float(r[j0 + j]) * inv, hv[j], lv[j]);
                uint32_t so = SMEM_SWIZZLE_64B((uint32_t)(rr * 64 + j0 * 2));
                *(uint4*)((char*)g_chh + tb + so) = *(uint4*)hv;
                *(uint4*)((char*)g_cll + tb + so) = *(uint4*)lv;
            }
        }
        TCGEN05_FENCE_BEFORE();
    }

    __syncthreads();
    if (tid == 0) {
        MBARRIER_INVAL(smb + 64);
        MBARRIER_INVAL(smb + 80);
#pragma unroll
        for (int s = 0; s < 2; ++s) {
            MBARRIER_INVAL(smb + 96 + 16 * s);
            MBARRIER_INVAL(smb + 128 + 16 * s);
            MBARRIER_INVAL(smb + 192 + 16 * s);
            MBARRIER_INVAL(smb + 224 + 16 * s);
        }
    }
    __syncthreads();
    if (wid == 0) {
        TCGEN05_RELINQUISH();
        TCGEN05_DEALLOC(tmem, 512);
    }
#endif  // HAS_TCGEN05
}

// ============================================================
extern "C" void kernel_launch(void* const* d_in, const int* in_sizes, int n_in,
                              void* d_out, int out_size)
{
    const float* x    = (const float*)d_in[0];
    const float* mask = (const float*)d_in[1];
    const float* Wq   = (const float*)d_in[2];
    const float* bq   = (const float*)d_in[3];
    const float* Wk   = (const float*)d_in[4];
    const float* bk   = (const float*)d_in[5];
    const float* Wv   = (const float*)d_in[6];
    const float* bv   = (const float*)d_in[7];
    const float* Wo   = (const float*)d_in[8];
    const float* bo   = (const float*)d_in[9];
    float* out = (float*)d_out;

    const int TOTAL8 = XN8 + 4 * WN8;

    cudaFuncSetAttribute(gemm_tc, cudaFuncAttributeMaxDynamicSharedMemorySize, GEMM_SMEM);
    cudaFuncSetAttribute(attn_tc, cudaFuncAttributeMaxDynamicSharedMemorySize, ATTN_SMEM);

    split_all<<<TOTAL8 / 256, 256>>>(x, Wq, Wk, Wv, Wo);
    gemm_tc<<<dim3(8, 16, 3), 256, GEMM_SMEM>>>(0, bq, bk, bv, bo, out);
    attn_tc<<<dim3(16, 32), 320, ATTN_SMEM>>>(mask);
    gemm_tc<<<dim3(8, 16, 1), 256, GEMM_SMEM>>>(3, bq, bk, bv, bo, out);
}

// round 17
// speedup vs baseline: 2.1146x; 1.3394x over previous
#include <cuda_runtime.h>
#include <cuda_bf16.h>
#include <cuda_fp16.h>
#include <cstdint>

#define D_MODEL 2048
#define SEQ     2048
#define BATCH   2
#define NHEADS  16
#define HDIM    128
#define M_TOK   (BATCH*SEQ)   // 4096

#if defined(__CUDA_ARCH_FEAT_SM103_ALL) || defined(__CUDA_ARCH_FEAT_SM100_ALL) || \
    (defined(__CUDA_ARCH_SPECIFIC__) && (__CUDA_ARCH_SPECIFIC__ >= 1000))
#define HAS_TCGEN05 1
#else
#define HAS_TCGEN05 0
#endif

// ---- persistent scratch ----
// fp16 GEMM operands (QKV projections): 8KB tiles (128r x 32k, 64B rows, SW64)
__device__ __half g_xf[M_TOK * D_MODEL];
__device__ __half g_wf[3][D_MODEL * D_MODEL];
// bf16 hi/lo operands (O projection): same tile format
__device__ __nv_bfloat16 g_chh[M_TOK * D_MODEL];   // packed ctx (written by attn)
__device__ __nv_bfloat16 g_cll[M_TOK * D_MODEL];
__device__ __nv_bfloat16 g_w3h[D_MODEL * D_MODEL];
__device__ __nv_bfloat16 g_w3l[D_MODEL * D_MODEL];

// attention operands (SW128 128B-row formats, bf16 hi/lo)
__device__ __nv_bfloat16 g_aqh[M_TOK * D_MODEL];   // Q tiles: [bh][rt16][2ch x 16KB]
__device__ __nv_bfloat16 g_aql[M_TOK * D_MODEL];
__device__ __nv_bfloat16 g_akh[M_TOK * D_MODEL];   // K tiles: [bh][kt32][2ch x 8KB]
__device__ __nv_bfloat16 g_akl[M_TOK * D_MODEL];
__device__ __nv_bfloat16 g_avh[M_TOK * D_MODEL];   // V^T tiles: [bh][kt32][16KB]
__device__ __nv_bfloat16 g_avl[M_TOK * D_MODEL];

// ============================================================
// PTX helpers
// ============================================================
__device__ __forceinline__ uint32_t smem_u32(const void* p) {
    uint32_t a;
    asm("{ .reg .u64 t; cvta.to.shared.u64 t, %1; cvt.u32.u64 %0, t; }" : "=r"(a) : "l"(p));
    return a;
}
__device__ __forceinline__ uint32_t elect_one_pred() {
    uint32_t p;
    asm volatile("{ .reg .pred p; elect.sync _|p, 0xFFFFFFFF; selp.b32 %0, 1, 0, p; }" : "=r"(p));
    return p;
}
static constexpr uint64_t SMEM_DESC_BASE_SW128 =
    (uint64_t(2) << 61) | (uint64_t(1) << 46) | (uint64_t(64) << 32) | (uint64_t(1) << 16);
static constexpr uint64_t SMEM_DESC_BASE_SW64 =
    (uint64_t(4) << 61) | (uint64_t(1) << 46) | (uint64_t(32) << 32) | (uint64_t(1) << 16);
#define MAKE_SMEM_DESC(base_addr) \
    (SMEM_DESC_BASE_SW128 | ((uint64_t)((base_addr) >> 4) & 0x3FFF))
#define MAKE_SMEM_DESC_SW64(base_addr) \
    (SMEM_DESC_BASE_SW64 | ((uint64_t)((base_addr) >> 4) & 0x3FFF))
#define SMEM_SWIZZLE_128B(off) ((off) ^ (((off) >> 3) & 0x70))
#define SMEM_SWIZZLE_64B(off)  ((off) ^ (((off) >> 3) & 0x30))

#define MBARRIER_INIT(mbar, count) \
    asm volatile("mbarrier.init.shared.b64 [%0], %1;" \
                 :: "r"((uint32_t)(mbar)), "r"((uint32_t)(count)) : "memory")
#define MBARRIER_INVAL(mbar) \
    asm volatile("mbarrier.inval.shared.b64 [%0];" :: "r"((uint32_t)(mbar)) : "memory")
#define MBARRIER_EXPECT_TX(mbar, bytes) \
    asm volatile("mbarrier.arrive.expect_tx.shared.b64 _, [%0], %1;" \
                 :: "r"((uint32_t)(mbar)), "r"((uint32_t)(bytes)) : "memory")
#define MBARRIER_ARRIVE(mbar) \
    asm volatile("mbarrier.arrive.shared.b64 _, [%0];" :: "r"((uint32_t)(mbar)) : "memory")
#define MBARRIER_WAIT_PARITY(mbar, parity) do {                                          \
    uint32_t _m = (uint32_t)(mbar);                                                      \
    uint32_t _p = (uint32_t)(parity);                                                    \
    uint32_t _done;                                                                      \
    asm volatile("{ .reg .pred p; mbarrier.try_wait.parity.acquire.cta.shared::cta.b64 " \
                 "p, [%1], %2; selp.b32 %0, 1, 0, p; }"                                  \
                 : "=r"(_done) : "r"(_m), "r"(_p) : "memory");                           \
    if (!_done) {                                                                        \
        asm volatile("{ .reg .pred P1; WL_%=: "                                          \
                     "mbarrier.try_wait.parity.acquire.cta.shared::cta.b64 P1, [%0], %1, 0x989680; " \
                     "@P1 bra.uni WD_%=; bra.uni WL_%=; WD_%=: }"                        \
                     :: "r"(_m), "r"(_p) : "memory");                                    \
    }                                                                                    \
} while (0)

#define BULK_CP(dst_smem, src_gmem, bytes, mbar) \
    asm volatile("cp.async.bulk.shared::cluster.global.mbarrier::complete_tx::bytes " \
                 "[%0], [%1], %2, [%3];" \
                 :: "r"((uint32_t)(dst_smem)), "l"(src_gmem), "r"((uint32_t)(bytes)), \
                    "r"((uint32_t)(mbar)) : "memory")
#define BULK_CP_S2G(dst_gmem, src_smem, bytes) \
    asm volatile("cp.async.bulk.global.shared::cta.bulk_group [%0], [%1], %2;" \
                 :: "l"(dst_gmem), "r"((uint32_t)(src_smem)), "r"((uint32_t)(bytes)) : "memory")
#define BULK_COMMIT() asm volatile("cp.async.bulk.commit_group;" ::: "memory")
#define BULK_WAIT0()  asm volatile("cp.async.bulk.wait_group 0;" ::: "memory")
#define FENCE_PROXY_ASYNC() asm volatile("fence.proxy.async;" ::: "memory")

#if HAS_TCGEN05
#define TCGEN05_ALLOC(smem_addr, nCols) \
    asm volatile("tcgen05.alloc.cta_group::1.sync.aligned.shared::cta.b32 [%0], %1;" \
                 :: "r"((uint32_t)(smem_addr)), "r"((uint32_t)(nCols)) : "memory")
#define TCGEN05_DEALLOC(tmem_addr, nCols) \
    asm volatile("tcgen05.dealloc.cta_group::1.sync.aligned.b32 %0, %1;" \
                 :: "r"(tmem_addr), "r"((uint32_t)(nCols)))
#define TCGEN05_RELINQUISH() \
    asm volatile("tcgen05.relinquish_alloc_permit.cta_group::1.sync.aligned;")
#define TCGEN05_COMMIT(mbar) \
    asm volatile("tcgen05.commit.cta_group::1.mbarrier::arrive::one.shared::cluster.b64 [%0];" \
                 :: "r"((uint32_t)(mbar)) : "memory")
#define TCGEN05_FENCE_AFTER() \
    asm volatile("tcgen05.fence::after_thread_sync;" ::: "memory")
#define TCGEN05_FENCE_BEFORE() \
    asm volatile("tcgen05.fence::before_thread_sync;" ::: "memory")
#define TCGEN05_WAIT_LD() \
    asm volatile("tcgen05.wait::ld.sync.aligned;" ::: "memory")
#define TCGEN05_WAIT_ST() \
    asm volatile("tcgen05.wait::st.sync.aligned;" ::: "memory")

#define TCGEN05_LD_32X32B_X32(r, tmem_addr) \
    asm volatile( \
        "tcgen05.ld.sync.aligned.32x32b.x32.b32 " \
        "{%0, %1, %2, %3, %4, %5, %6, %7, " \
        " %8, %9, %10, %11, %12, %13, %14, %15, " \
        " %16, %17, %18, %19, %20, %21, %22, %23, " \
        " %24, %25, %26, %27, %28, %29, %30, %31}, [%32];" \
        : "=r"((r)[0]),  "=r"((r)[1]),  "=r"((r)[2]),  "=r"((r)[3]), \
          "=r"((r)[4]),  "=r"((r)[5]),  "=r"((r)[6]),  "=r"((r)[7]), \
          "=r"((r)[8]),  "=r"((r)[9]),  "=r"((r)[10]), "=r"((r)[11]), \
          "=r"((r)[12]), "=r"((r)[13]), "=r"((r)[14]), "=r"((r)[15]), \
          "=r"((r)[16]), "=r"((r)[17]), "=r"((r)[18]), "=r"((r)[19]), \
          "=r"((r)[20]), "=r"((r)[21]), "=r"((r)[22]), "=r"((r)[23]), \
          "=r"((r)[24]), "=r"((r)[25]), "=r"((r)[26]), "=r"((r)[27]), \
          "=r"((r)[28]), "=r"((r)[29]), "=r"((r)[30]), "=r"((r)[31]) \
        : "r"(tmem_addr))

#define TCGEN05_ST_32X32B_X32(tmem_addr, r) \
    asm volatile( \
        "tcgen05.st.sync.aligned.32x32b.x32.b32 [%0], " \
        "{%1, %2, %3, %4, %5, %6, %7, %8, " \
        " %9, %10, %11, %12, %13, %14, %15, %16, " \
        " %17, %18, %19, %20, %21, %22, %23, %24, " \
        " %25, %26, %27, %28, %29, %30, %31, %32};" \
        :: "r"(tmem_addr), \
           "r"((r)[0]),  "r"((r)[1]),  "r"((r)[2]),  "r"((r)[3]), \
           "r"((r)[4]),  "r"((r)[5]),  "r"((r)[6]),  "r"((r)[7]), \
           "r"((r)[8]),  "r"((r)[9]),  "r"((r)[10]), "r"((r)[11]), \
           "r"((r)[12]), "r"((r)[13]), "r"((r)[14]), "r"((r)[15]), \
           "r"((r)[16]), "r"((r)[17]), "r"((r)[18]), "r"((r)[19]), \
           "r"((r)[20]), "r"((r)[21]), "r"((r)[22]), "r"((r)[23]), \
           "r"((r)[24]), "r"((r)[25]), "r"((r)[26]), "r"((r)[27]), \
           "r"((r)[28]), "r"((r)[29]), "r"((r)[30]), "r"((r)[31]) \
        : "memory")

#define TCGEN05_ST_32X32B_X16(tmem_addr, r) \
    asm volatile( \
        "tcgen05.st.sync.aligned.32x32b.x16.b32 [%0], " \
        "{%1, %2, %3, %4, %5, %6, %7, %8, " \
        " %9, %10, %11, %12, %13, %14, %15, %16};" \
        :: "r"(tmem_addr), \
           "r"((r)[0]),  "r"((r)[1]),  "r"((r)[2]),  "r"((r)[3]), \
           "r"((r)[4]),  "r"((r)[5]),  "r"((r)[6]),  "r"((r)[7]), \
           "r"((r)[8]),  "r"((r)[9]),  "r"((r)[10]), "r"((r)[11]), \
           "r"((r)[12]), "r"((r)[13]), "r"((r)[14]), "r"((r)[15]) \
        : "memory")

__device__ __forceinline__ void mma_f16_ss(uint32_t d_tmem, uint64_t a_desc, uint64_t b_desc,
                                           uint32_t idesc, uint32_t enable) {
    asm volatile(
        "{\n\t"
        ".reg .pred p;\n\t"
        "setp.ne.u32 p, %4, 0;\n\t"
        "tcgen05.mma.cta_group::1.kind::f16 [%0], %1, %2, %3, {%5, %5, %5, %5}, p;\n\t"
        "}"
        :: "r"(d_tmem), "l"(a_desc), "l"(b_desc), "r"(idesc), "r"(enable), "r"(0u)
        : "memory");
}
__device__ __forceinline__ void mma_f16_ts(uint32_t d_tmem, uint32_t a_tmem, uint64_t b_desc,
                                           uint32_t idesc, uint32_t enable) {
    asm volatile(
        "{\n\t"
        ".reg .pred p;\n\t"
        "setp.ne.u32 p, %4, 0;\n\t"
        "tcgen05.mma.cta_group::1.kind::f16 [%0], [%1], %2, %3, {%5, %5, %5, %5}, p;\n\t"
        "}"
        :: "r"(d_tmem), "r"(a_tmem), "l"(b_desc), "r"(idesc), "r"(enable), "r"(0u)
        : "memory");
}
#endif  // HAS_TCGEN05

__device__ __forceinline__ void split_bf16(float f, __nv_bfloat16& h, __nv_bfloat16& l) {
    h = __float2bfloat16(f);
    l = __float2bfloat16(f - __bfloat162float(h));
}

// ============================================================
// Merged split+pack, 8KB-tile SW64 format:
//   seg 0: x -> fp16;  segs 1-3: W0..W2 -> fp16;  seg 4: W3 -> bf16 hi/lo
// ============================================================
#define XN8 (M_TOK * D_MODEL / 8)
#define WN8 (D_MODEL * D_MODEL / 8)

__global__ __launch_bounds__(256) void split_all(
    const float* __restrict__ x, const float* __restrict__ W0,
    const float* __restrict__ W1, const float* __restrict__ W2,
    const float* __restrict__ W3)
{
    int i = blockIdx.x * blockDim.x + threadIdx.x;
    const float* src;
    int nrt, li, kind;     // kind 0 = fp16, 1 = bf16 hi/lo
    __half* f16dst = nullptr;
    __nv_bfloat16 *hi = nullptr, *lo = nullptr;
    if (i < XN8) {
        src = x; f16dst = g_xf; nrt = 32; li = i; kind = 0;
    } else {
        int w = (i - XN8) >> 19;
        li = (i - XN8) & (WN8 - 1);
        nrt = 16;
        if (w < 3) {
            src = (w == 0) ? W0 : (w == 1) ? W1 : W2;
            f16dst = g_wf[w]; kind = 0;
        } else {
            src = W3; hi = g_w3h; lo = g_w3l; kind = 1;
        }
    }
    int elem = li * 8;
    int row = elem >> 11;
    int col = elem & 2047;
    int rt = row >> 7, r = row & 127;
    int c  = col >> 5, kc = col & 31;
    size_t tb = ((size_t)(c * nrt + rt)) << 13;
    uint32_t so = SMEM_SWIZZLE_64B((uint32_t)(r * 64 + kc * 2));

    float4 v0 = ((const float4*)src)[(size_t)li * 2];
    float4 v1 = ((const float4*)src)[(size_t)li * 2 + 1];
    float f[8] = {v0.x, v0.y, v0.z, v0.w, v1.x, v1.y, v1.z, v1.w};
    if (kind == 0) {
        __align__(16) __half h[8];
#pragma unroll
        for (int j = 0; j < 8; j++) h[j] = __float2half(f[j]);
        *(uint4*)((char*)f16dst + tb + so) = *(uint4*)h;
    } else {
        __align__(16) __nv_bfloat16 h[8], l[8];
#pragma unroll
        for (int j = 0; j < 8; j++) split_bf16(f[j], h[j], l[j]);
        *(uint4*)((char*)hi + tb + so) = *(uint4*)h;
        *(uint4*)((char*)lo + tb + so) = *(uint4*)l;
    }
}

// ============================================================
// tcgen05 GEMM, 256x256/CTA, warp-specialized (w0 MMA, w1 loader).
// Modes 0/1/2 (Q/K/V proj): fp16 single-pass, 32KB chunks, 6 stages.
// Mode 3 (O proj): bf16 hi/lo 3-term, 64KB chunks, 3 stages.
// ============================================================
#define NCH  64
#define TIL8 8192
#define SMB0 1024
#define GEMM_SMEM (SMB0 + 6 * 32768)    // 197632 (also covers 3 x 64KB)
#define IDESC_BF16 0x8400490u           // F32 accum, BF16xBF16, M=128, N=256
#define IDESC_FP16 0x8400010u           // F32 accum, F16xF16,  M=128, N=256
#define NRT_A 32

__global__ __launch_bounds__(256) void gemm_tc(
    int mode_base, const float* __restrict__ b0, const float* __restrict__ b1,
    const float* __restrict__ b2, const float* __restrict__ b3,
    float* __restrict__ out)
{
#if HAS_TCGEN05
    extern __shared__ char sm[];
    const uint32_t smb = smem_u32(sm);
    const int tid = threadIdx.x;
    const int wid = tid >> 5;
    const int lid = tid & 31;
    const int rp = blockIdx.y;
    const int bx = blockIdx.x;
    const int mode = mode_base + blockIdx.z;

    const float* bias = (mode == 0) ? b0 : (mode == 1) ? b1 : (mode == 2) ? b2 : b3;
    const float alpha = (mode == 0) ? 0.08838834764831845f : 1.0f;

    if (wid == 0) TCGEN05_ALLOC(smb + 0, 512);
    if (tid == 0) {
#pragma unroll
        for (int s = 0; s < 6; ++s) {
            MBARRIER_INIT(smb + 64 + 16 * s, 1);     // full (tx)
            MBARRIER_INIT(smb + 160 + 16 * s, 1);    // mma commit
        }
    }
    __syncthreads();

    uint32_t tmem;
    asm volatile("ld.shared.b32 %0, [%1];" : "=r"(tmem) : "r"(smb + 0));

    if (mode < 3) {
        // ---------------- fp16 single-pass: 32KB chunk, 6 stages ----------------
        const __half* A = g_xf;
        const __half* B = g_wf[mode];
#define LOAD_F16(c, s)                                                          \
        do {                                                                    \
            uint32_t st = smb + SMB0 + (s) * 32768;                             \
            uint32_t fb = smb + 64 + 16 * (s);                                  \
            size_t ao = ((size_t)((c) * 32 + 2 * rp)) << 13;                    \
            size_t bo = ((size_t)((c) * 16 + 2 * bx)) << 13;                    \
            MBARRIER_EXPECT_TX(fb, 32768);                                      \
            BULK_CP(st,          (const char*)A + ao, 16384, fb);               \
            BULK_CP(st + 16384,  (const char*)B + bo, 16384, fb);               \
        } while (0)

        if (wid == 1 && elect_one_pred()) {
#pragma unroll
            for (int s = 0; s < 6; ++s) LOAD_F16(s, s);
            for (int c = 6; c < NCH; ++c) {
                int pc = c - 6;
                MBARRIER_WAIT_PARITY(smb + 160 + 16 * (pc % 6), (pc / 6) & 1);
                LOAD_F16(c, c % 6);
            }
        }
        if (wid == 0 && elect_one_pred()) {
            for (int c = 0; c < NCH; ++c) {
                int s = c % 6, ph = (c / 6) & 1;
                uint32_t st = smb + SMB0 + s * 32768;
                MBARRIER_WAIT_PARITY(smb + 64 + 16 * s, ph);
                uint64_t dB = MAKE_SMEM_DESC_SW64(st + 16384);
#pragma unroll
                for (int ks = 0; ks < 2; ++ks) {
#pragma unroll
                    for (int t = 0; t < 2; ++t) {
                        uint64_t dA = MAKE_SMEM_DESC_SW64(st + t * TIL8) + ks * 2;
                        mma_f16_ss(tmem + t * 256, dA, dB + ks * 2, IDESC_FP16, (c | ks) != 0);
                    }
                }
                TCGEN05_COMMIT(smb + 160 + 16 * s);
            }
            MBARRIER_WAIT_PARITY(smb + 160 + 16 * ((NCH - 1) % 6), ((NCH - 1) / 6) & 1);
        }
#undef LOAD_F16
    } else {
        // ---------------- bf16 hi/lo 3-term: 64KB chunk, 3 stages ----------------
        const __nv_bfloat16* Ah = g_chh;
        const __nv_bfloat16* Al = g_cll;
        const __nv_bfloat16* Bh = g_w3h;
        const __nv_bfloat16* Bl = g_w3l;
#define LOAD_BF(c, s)                                                           \
        do {                                                                    \
            uint32_t st = smb + SMB0 + (s) * 65536;                             \
            uint32_t fb = smb + 64 + 16 * (s);                                  \
            size_t ao = ((size_t)((c) * 32 + 2 * rp)) << 13;                    \
            size_t bo = ((size_t)((c) * 16 + 2 * bx)) << 13;                    \
            MBARRIER_EXPECT_TX(fb, 65536);                                      \
            BULK_CP(st,             (const char*)Ah + ao, 2 * TIL8, fb);        \
            BULK_CP(st + 2 * TIL8,  (const char*)Al + ao, 2 * TIL8, fb);        \
            BULK_CP(st + 4 * TIL8,  (const char*)Bh + bo, 2 * TIL8, fb);        \
            BULK_CP(st + 6 * TIL8,  (const char*)Bl + bo, 2 * TIL8, fb);        \
        } while (0)

        if (wid == 1 && elect_one_pred()) {
            LOAD_BF(0, 0);
            LOAD_BF(1, 1);
            LOAD_BF(2, 2);
            for (int c = 3; c < NCH; ++c) {
                int pc = c - 3;
                MBARRIER_WAIT_PARITY(smb + 160 + 16 * (pc % 3), (pc / 3) & 1);
                LOAD_BF(c, c % 3);
            }
        }
        if (wid == 0 && elect_one_pred()) {
            for (int c = 0; c < NCH; ++c) {
                int s = c % 3, ph = (c / 3) & 1;
                uint32_t st = smb + SMB0 + s * 65536;
                MBARRIER_WAIT_PARITY(smb + 64 + 16 * s, ph);
                uint64_t dBh = MAKE_SMEM_DESC_SW64(st + 4 * TIL8);
                uint64_t dBl = MAKE_SMEM_DESC_SW64(st + 6 * TIL8);
#pragma unroll
                for (int ks = 0; ks < 2; ++ks) {
#pragma unroll
                    for (int t = 0; t < 2; ++t) {
                        uint64_t dAh = MAKE_SMEM_DESC_SW64(st + t * TIL8) + ks * 2;
                        uint64_t dAl = MAKE_SMEM_DESC_SW64(st + 2 * TIL8 + t * TIL8) + ks * 2;
                        uint32_t acc = tmem + t * 256;
                        mma_f16_ss(acc, dAh, dBh + ks * 2, IDESC_BF16, (c | ks) != 0);
                        mma_f16_ss(acc, dAl, dBh + ks * 2, IDESC_BF16, 1);
                        mma_f16_ss(acc, dAh, dBl + ks * 2, IDESC_BF16, 1);
                    }
                }
                TCGEN05_COMMIT(smb + 160 + 16 * s);
            }
            MBARRIER_WAIT_PARITY(smb + 160 + 16 * ((NCH - 1) % 3), ((NCH - 1) / 3) & 1);
        }
#undef LOAD_BF
    }
    __syncthreads();
    TCGEN05_FENCE_AFTER();

    const int wg = wid >> 2;
    const int sub = wid & 3;
    const int hd = bx * 2 + wg;

    if (mode == 2) {
        // fused V^T pack epilogue (validated R15)
        const int token_local = sub * 32 + lid;
        const int kt2 = token_local >> 6;
        const int sc = token_local & 63;
        char* tbuf = sm + SMB0 + (size_t)(wg * 2 + kt2) * 32768;
#pragma unroll
        for (int t = 0; t < 2; ++t) {
#pragma unroll
            for (int cb = 0; cb < 4; ++cb) {
                uint32_t r[32];
                TCGEN05_LD_32X32B_X32(r, tmem + t * 256 + wg * 128 + cb * 32);
                TCGEN05_WAIT_LD();
                int n0 = bx * 256 + wg * 128 + cb * 32;
#pragma unroll
                for (int j = 0; j < 32; ++j) {
                    float f = __uint_as_float(r[j]) + bias[n0 + j];
                    __nv_bfloat16 hh, ll;
                    split_bf16(f, hh, ll);
                    int d = cb * 32 + j;
                    uint32_t off = SMEM_SWIZZLE_128B((uint32_t)(d * 128 + sc * 2));
                    *(__nv_bfloat16*)(tbuf + off) = hh;
                    *(__nv_bfloat16*)(tbuf + 16384 + off) = ll;
                }
            }
            __syncthreads();
            FENCE_PROXY_ASYNC();
            if (tid < 4) {
                int wg_t = tid >> 1, kt2g = tid & 1;
                int m0 = (rp * 2 + t) * 128;
                int b_ = m0 >> 11;
                int ktg = ((m0 & 2047) >> 6) + kt2g;
                int bh = b_ * 16 + bx * 2 + wg_t;
                size_t dst = ((size_t)(bh * 32 + ktg)) << 14;
                uint32_t sbuf = smb + SMB0 + (uint32_t)tid * 32768;
                BULK_CP_S2G((char*)g_avh + dst, sbuf, 16384);
                BULK_CP_S2G((char*)g_avl + dst, sbuf + 16384, 16384);
                BULK_COMMIT();
                BULK_WAIT0();
            }
            __syncthreads();
        }
        TCGEN05_FENCE_BEFORE();
    } else {
        __align__(16) __nv_bfloat16 hv[8], lv[8];
#pragma unroll
        for (int t = 0; t < 2; ++t) {
            const int m = (rp * 2 + t) * 128 + sub * 32 + lid;
            const int b_ = m >> 11, s_ = m & 2047;
            const int bh2 = b_ * 16 + hd;
#pragma unroll
            for (int cb = 0; cb < 4; ++cb) {
                uint32_t r[32];
                TCGEN05_LD_32X32B_X32(r, tmem + t * 256 + wg * 128 + cb * 32);
                TCGEN05_WAIT_LD();
                int n0 = bx * 256 + wg * 128 + cb * 32;

                if (mode == 3) {
                    float* crow = out + (size_t)m * D_MODEL;
#pragma unroll
                    for (int j = 0; j < 32; j += 4) {
                        float4 o;
                        o.x = __uint_as_float(r[j + 0]) + bias[n0 + j + 0];
                        o.y = __uint_as_float(r[j + 1]) + bias[n0 + j + 1];
                        o.z = __uint_as_float(r[j + 2]) + bias[n0 + j + 2];
                        o.w = __uint_as_float(r[j + 3]) + bias[n0 + j + 3];
                        *(float4*)(crow + n0 + j) = o;
                    }
                } else {
                    size_t tb;
                    uint32_t rr;
                    char *dh, *dl;
                    if (mode == 0) {
                        int rt2 = s_ >> 7; rr = s_ & 127;
                        tb = ((size_t)((bh2 * 16 + rt2) * 2 + (cb >> 1))) << 14;
                        dh = (char*)g_aqh + tb; dl = (char*)g_aql + tb;
                    } else {
                        int kt = s_ >> 6; rr = s_ & 63;
                        tb = ((size_t)((bh2 * 32 + kt) * 2 + (cb >> 1))) << 13;
                        dh = (char*)g_akh + tb; dl = (char*)g_akl + tb;
                    }
                    int kcb = (cb & 1) * 32;
#pragma unroll
                    for (int j0 = 0; j0 < 32; j0 += 8) {
#pragma unroll
                        for (int j = 0; j < 8; ++j) {
                            float f = (__uint_as_float(r[j0 + j]) + bias[n0 + j0 + j]) * alpha;
                            split_bf16(f, hv[j], lv[j]);
                        }
                        uint32_t so = SMEM_SWIZZLE_128B((uint32_t)(rr * 128 + (kcb + j0) * 2));
                        *(uint4*)(dh + so) = *(uint4*)hv;
                        *(uint4*)(dl + so) = *(uint4*)lv;
                    }
                }
            }
        }
        TCGEN05_FENCE_BEFORE();
    }

    __syncthreads();
    if (tid == 0) {
#pragma unroll
        for (int s = 0; s < 6; ++s) {
            MBARRIER_INVAL(smb + 64 + 16 * s);
            MBARRIER_INVAL(smb + 160 + 16 * s);
        }
    }
    __syncthreads();
    if (wid == 0) {
        TCGEN05_RELINQUISH();
        TCGEN05_DEALLOC(tmem, 512);
    }
#endif
}

// ============================================================
// tcgen05 flash attention (R16 warp-specialized version, unchanged)
// ============================================================
#define AOFF_LBUF 1024
#define AOFF_MASK 2048
#define AOFF_K    10240
#define AOFF_V    75776
#define AOFF_QS   (AOFF_V + 65536)
#define ATTN_SMEM 206848
#define IDESC_S   0x8100490u
#define IDESC_PV  0x8200490u

__global__ __launch_bounds__(320) void attn_tc(const float* __restrict__ mask)
{
#if HAS_TCGEN05
    extern __shared__ char sm[];
    const uint32_t smb = smem_u32(sm);
    const int tid = threadIdx.x;
    const int wid = tid >> 5;
    const int lid = tid & 31;
    const int rt = blockIdx.x;
    const int bh = blockIdx.y;
    const int b = bh >> 4;

    if (wid == 0) TCGEN05_ALLOC(smb + 0, 512);
    if (tid == 0) {
        MBARRIER_INIT(smb + 64, 1);    // qbar (tx)
        MBARRIER_INIT(smb + 80, 4);    // qdone
#pragma unroll
        for (int s = 0; s < 2; ++s) {
            MBARRIER_INIT(smb + 96 + 16 * s, 1);    // full (tx)
            MBARRIER_INIT(smb + 128 + 16 * s, 1);   // s_full (commit)
            MBARRIER_INIT(smb + 192 + 16 * s, 8);   // p_ready
            MBARRIER_INIT(smb + 224 + 16 * s, 1);   // pv_done (commit)
        }
    }
    for (int j = tid; j < SEQ; j += 320) {
        float mv = mask[b * SEQ + j];
        ((float*)(sm + AOFF_MASK))[j] = (1.0f - mv) * -1e30f;
    }
    __syncthreads();

    uint32_t tmem;
    asm volatile("ld.shared.b32 %0, [%1];" : "=r"(tmem) : "r"(smb + 0));

#define LOADKV(c)                                                          \
    do {                                                                   \
        size_t kb = ((size_t)(bh * 32 + (c))) << 14;                       \
        uint32_t kst = smb + AOFF_K + ((c) & 1) * 32768;                   \
        uint32_t vst = smb + AOFF_V + ((c) & 3) * 32768;                   \
        uint32_t fb = smb + 96 + 16 * ((c) & 1);                           \
        MBARRIER_EXPECT_TX(fb, 65536);                                     \
        BULK_CP(kst,         (const char*)g_akh + kb, 16384, fb);          \
        BULK_CP(kst + 16384, (const char*)g_akl + kb, 16384, fb);          \
        BULK_CP(vst,         (const char*)g_avh + kb, 16384, fb);          \
        BULK_CP(vst + 16384, (const char*)g_avl + kb, 16384, fb);          \
    } while (0)

    // ---------------- loader warp ----------------
    if (wid == 9) {
        if (elect_one_pred()) {
            {
                size_t qb = ((size_t)(bh * 16 + rt)) << 15;
                MBARRIER_EXPECT_TX(smb + 64, 65536);
                BULK_CP(smb + AOFF_QS,         (const char*)g_aqh + qb, 32768, smb + 64);
                BULK_CP(smb + AOFF_QS + 32768, (const char*)g_aql + qb, 32768, smb + 64);
                LOADKV(0);
                LOADKV(1);
            }
            for (int c = 2; c < 32; ++c) {
                MBARRIER_WAIT_PARITY(smb + 128 + 16 * ((c - 2) & 1), ((c - 2) >> 1) & 1);
                if (c >= 4)
                    MBARRIER_WAIT_PARITY(smb + 224 + 16 * ((c - 4) & 1), ((c - 4) >> 1) & 1);
                LOADKV(c);
            }
        }
    }

    // ---------------- MMA warp ----------------
    if (wid == 8) {
        if (elect_one_pred()) {
            MBARRIER_WAIT_PARITY(smb + 80, 0);
            TCGEN05_FENCE_AFTER();

            const uint32_t qh = tmem + 384, ql = tmem + 448;

            for (int i = 0; i < 32; ++i) {
                const int sb = i & 1;
                MBARRIER_WAIT_PARITY(smb + 96 + 16 * sb, (i >> 1) & 1);
                {
                    uint32_t kst = smb + AOFF_K + sb * 32768;
                    uint32_t sreg = tmem + sb * 64;
#pragma unroll
                    for (int st = 0; st < 8; ++st) {
                        uint64_t bh_ = MAKE_SMEM_DESC(kst + (st >> 2) * 8192) + (st & 3) * 2;
                        uint64_t bl_ = MAKE_SMEM_DESC(kst + 16384 + (st >> 2) * 8192) + (st & 3) * 2;
                        mma_f16_ts(sreg, qh + st * 8, bh_, IDESC_S, st != 0);
                        mma_f16_ts(sreg, ql + st * 8, bh_, IDESC_S, 1);
                        mma_f16_ts(sreg, qh + st * 8, bl_, IDESC_S, 1);
                    }
                    TCGEN05_COMMIT(smb + 128 + 16 * sb);
                }
                if (i >= 1) {
                    const int j = i - 1, pb = j & 1, pj = (j >> 1) & 1;
                    MBARRIER_WAIT_PARITY(smb + 192 + 16 * pb, pj);
                    TCGEN05_FENCE_AFTER();
                    uint32_t vst = smb + AOFF_V + (j & 3) * 32768;
                    uint64_t dVh = MAKE_SMEM_DESC(vst);
                    uint64_t dVl = MAKE_SMEM_DESC(vst + 16384);
#pragma unroll
                    for (int ks = 0; ks < 4; ++ks) {
                        uint32_t ah = tmem + 256 + pb * 64 + ks * 8;
                        uint32_t al = tmem + 288 + pb * 64 + ks * 8;
                        mma_f16_ts(tmem + 128, ah, dVh + ks * 2, IDESC_PV, (j | ks) != 0);
                        mma_f16_ts(tmem + 128, al, dVh + ks * 2, IDESC_PV, 1);
                        mma_f16_ts(tmem + 128, ah, dVl + ks * 2, IDESC_PV, 1);
                    }
                    TCGEN05_COMMIT(smb + 224 + 16 * pb);
                }
            }
            {
                const int j = 31, pb = 1, pj = 1;
                MBARRIER_WAIT_PARITY(smb + 192 + 16 * pb, pj);
                TCGEN05_FENCE_AFTER();
                uint32_t vst = smb + AOFF_V + (j & 3) * 32768;
                uint64_t dVh = MAKE_SMEM_DESC(vst);
                uint64_t dVl = MAKE_SMEM_DESC(vst + 16384);
#pragma unroll
                for (int ks = 0; ks < 4; ++ks) {
                    uint32_t ah = tmem + 256 + pb * 64 + ks * 8;
                    uint32_t al = tmem + 288 + pb * 64 + ks * 8;
                    mma_f16_ts(tmem + 128, ah, dVh + ks * 2, IDESC_PV, 1);
                    mma_f16_ts(tmem + 128, al, dVh + ks * 2, IDESC_PV, 1);
                    mma_f16_ts(tmem + 128, ah, dVl + ks * 2, IDESC_PV, 1);
                }
                TCGEN05_COMMIT(smb + 224 + 16 * pb);
                MBARRIER_WAIT_PARITY(smb + 224 + 16 * pb, pj);
            }
        }
    }
#undef LOADKV

    // ---------------- softmax warps (8) ----------------
    if (wid < 8) {
        const int sub = wid & 3;
        const int hw  = wid >> 2;
        const uint32_t wo = (uint32_t)sub << 21;
        float l = 0.0f;

        if (wid < 4) {
            MBARRIER_WAIT_PARITY(smb + 64, 0);
            const int r = sub * 32 + lid;
#pragma unroll
            for (int part = 0; part < 4; ++part) {
                uint32_t base = AOFF_QS + (part >> 1) * 32768 + (part & 1) * 16384;
                uint32_t q32[32];
#pragma unroll
                for (int g = 0; g < 8; ++g) {
                    uint32_t off = base + SMEM_SWIZZLE_128B((uint32_t)(r * 128 + g * 16));
                    uint4 v = *(const uint4*)(sm + off);
                    q32[g * 4 + 0] = v.x; q32[g * 4 + 1] = v.y;
                    q32[g * 4 + 2] = v.z; q32[g * 4 + 3] = v.w;
                }
                uint32_t dst = tmem + 384 + (part >> 1) * 64 + (part & 1) * 32 + wo;
                TCGEN05_ST_32X32B_X32(dst, q32);
            }
            TCGEN05_WAIT_ST();
            TCGEN05_FENCE_BEFORE();
            if (elect_one_pred()) MBARRIER_ARRIVE(smb + 80);
        }

        const float* md_base = (const float*)(sm + AOFF_MASK);
        for (int i = 0; i < 32; ++i) {
            int s = i & 1, ph = (i >> 1) & 1;
            MBARRIER_WAIT_PARITY(smb + 128 + 16 * s, ph);
            TCGEN05_FENCE_AFTER();
            uint32_t r0[32];
            TCGEN05_LD_32X32B_X32(r0, tmem + s * 64 + hw * 32);
            TCGEN05_WAIT_LD();

            const float* md = md_base + i * 64 + hw * 32;
#pragma unroll
            for (int j = 0; j < 32; ++j) {
                float e = __expf(__uint_as_float(r0[j]) + md[j]);
                l += e;
                r0[j] = __float_as_uint(e);
            }
            uint32_t phv[16], plv[16];
#pragma unroll
            for (int p = 0; p < 16; ++p) {
                __nv_bfloat16 h0, h1, l0, l1;
                split_bf16(__uint_as_float(r0[2 * p]), h0, l0);
                split_bf16(__uint_as_float(r0[2 * p + 1]), h1, l1);
                __nv_bfloat162 hp(h0, h1), lp(l0, l1);
                phv[p] = *(uint32_t*)&hp;
                plv[p] = *(uint32_t*)&lp;
            }
            TCGEN05_ST_32X32B_X16(tmem + 256 + s * 64 + hw * 16 + wo, phv);
            TCGEN05_ST_32X32B_X16(tmem + 288 + s * 64 + hw * 16 + wo, plv);
            TCGEN05_WAIT_ST();
            TCGEN05_FENCE_BEFORE();
            if (elect_one_pred()) MBARRIER_ARRIVE(smb + 192 + 16 * s);
        }
        ((float*)(sm + AOFF_LBUF))[hw * 128 + sub * 32 + lid] = l;
    }

    __syncthreads();

    // epilogue: normalize O; write ctx in 8KB-tile SW64 bf16 hi/lo format
    if (wid < 8) {
        TCGEN05_FENCE_AFTER();
        const int sub = wid & 3;
        const int hw = wid >> 2;
        const uint32_t wo = (uint32_t)sub << 21;
        const int row = sub * 32 + lid;
        const float* lbuf = (const float*)(sm + AOFF_LBUF);
        float inv = 1.0f / (lbuf[row] + lbuf[128 + row]);
        int qrow = rt * 128 + row;
        int tok = b * 2048 + qrow;
        int rtt = tok >> 7, rr = tok & 127;
        int hh = bh & 15;
        __align__(16) __nv_bfloat16 hv[8], lv[8];
#pragma unroll
        for (int t = 0; t < 2; ++t) {
            int cb = hw * 2 + t;
            uint32_t r[32];
            TCGEN05_LD_32X32B_X32(r, tmem + 128 + cb * 32 + wo);
            TCGEN05_WAIT_LD();
            int c32 = hh * 4 + cb;
            size_t tb = ((size_t)(c32 * 32 + rtt)) << 13;
#pragma unroll
            for (int j0 = 0; j0 < 32; j0 += 8) {
#pragma unroll
                for (int j = 0; j < 8; ++j)
                    split_bf16(__uint_as_float(r[j0 + j]) * inv, hv[j], lv[j]);
                uint32_t so = SMEM_SWIZZLE_64B((uint32_t)(rr * 64 + j0 * 2));
                *(uint4*)((char*)g_chh + tb + so) = *(uint4*)hv;
                *(uint4*)((char*)g_cll + tb + so) = *(uint4*)lv;
            }
        }
        TCGEN05_FENCE_BEFORE();
    }

    __syncthreads();
    if (tid == 0) {
        MBARRIER_INVAL(smb + 64);
        MBARRIER_INVAL(smb + 80);
#pragma unroll
        for (int s = 0; s < 2; ++s) {
            MBARRIER_INVAL(smb + 96 + 16 * s);
            MBARRIER_INVAL(smb + 128 + 16 * s);
            MBARRIER_INVAL(smb + 192 + 16 * s);
            MBARRIER_INVAL(smb + 224 + 16 * s);
        }
    }
    __syncthreads();
    if (wid == 0) {
        TCGEN05_RELINQUISH();
        TCGEN05_DEALLOC(tmem, 512);
    }
#endif  // HAS_TCGEN05
}

// ============================================================
extern "C" void kernel_launch(void* const* d_in, const int* in_sizes, int n_in,
                              void* d_out, int out_size)
{
    const float* x    = (const float*)d_in[0];
    const float* mask = (const float*)d_in[1];
    const float* Wq   = (const float*)d_in[2];
    const float* bq   = (const float*)d_in[3];
    const float* Wk   = (const float*)d_in[4];
    const float* bk   = (const float*)d_in[5];
    const float* Wv   = (const float*)d_in[6];
    const float* bv   = (const float*)d_in[7];
    const float* Wo   = (const float*)d_in[8];
    const float* bo   = (const float*)d_in[9];
    float* out = (float*)d_out;

    const int TOTAL8 = XN8 + 4 * WN8;

    cudaFuncSetAttribute(gemm_tc, cudaFuncAttributeMaxDynamicSharedMemorySize, GEMM_SMEM);
    cudaFuncSetAttribute(attn_tc, cudaFuncAttributeMaxDynamicSharedMemorySize, ATTN_SMEM);

    split_all<<<TOTAL8 / 256, 256>>>(x, Wq, Wk, Wv, Wo);
    gemm_tc<<<dim3(8, 16, 3), 256, GEMM_SMEM>>>(0, bq, bk, bv, bo, out);
    attn_tc<<<dim3(16, 32), 320, ATTN_SMEM>>>(mask);
    gemm_tc<<<dim3(8, 16, 1), 256, GEMM_SMEM>>>(3, bq, bk, bv, bo, out);
}